// round 1
// baseline (speedup 1.0000x reference)
#include <cuda_runtime.h>
#include <cuda_bf16.h>
#include <math.h>

// Problem constants
#define BATCH 2
#define SEQ   2048
#define EMBED 2048
#define NH    16
#define NKV   4
#define HD    128
#define FF    5632
#define ROWS  (BATCH*SEQ)          // 4096
#define QKV_N ((NH + 2*NKV)*HD)    // 3072

// ---------------- scratch (static device globals; allocation-free) -------------
__device__ float g_norm[ROWS*EMBED];
__device__ float g_qkv [ROWS*QKV_N];
__device__ float g_attn[ROWS*EMBED];
__device__ float g_h2  [ROWS*EMBED];
__device__ float g_ff1 [ROWS*FF];
__device__ float g_ff2 [ROWS*FF];

// ---------------- rmsnorm ------------------------------------------------------
__global__ __launch_bounds__(256) void rmsnorm_kernel(
    const float* __restrict__ x, const float* __restrict__ w, float* __restrict__ o)
{
    int row = blockIdx.x;
    const float4* xr = (const float4*)(x + (size_t)row * EMBED);
    int t = threadIdx.x;
    float4 v0 = xr[t];
    float4 v1 = xr[t + 256];
    float ss = v0.x*v0.x + v0.y*v0.y + v0.z*v0.z + v0.w*v0.w
             + v1.x*v1.x + v1.y*v1.y + v1.z*v1.z + v1.w*v1.w;
    #pragma unroll
    for (int m = 16; m; m >>= 1) ss += __shfl_xor_sync(0xffffffffu, ss, m);
    __shared__ float red[8];
    if ((t & 31) == 0) red[t >> 5] = ss;
    __syncthreads();
    float tot = red[0]+red[1]+red[2]+red[3]+red[4]+red[5]+red[6]+red[7];
    float r = rsqrtf(tot * (1.0f/EMBED) + 1e-5f);
    const float4* wr = (const float4*)w;
    float4 w0 = wr[t], w1 = wr[t + 256];
    float4* orow = (float4*)(o + (size_t)row * EMBED);
    orow[t]       = make_float4(v0.x*r*w0.x, v0.y*r*w0.y, v0.z*r*w0.z, v0.w*r*w0.w);
    orow[t + 256] = make_float4(v1.x*r*w1.x, v1.y*r*w1.y, v1.z*r*w1.z, v1.w*r*w1.w);
}

// ---------------- RoPE (in-place on qkv buffer, q + k heads) -------------------
__global__ __launch_bounds__(256) void rope_kernel(
    float* __restrict__ qkv, const float* __restrict__ freqs)
{
    int idx = blockIdx.x * 256 + threadIdx.x;     // ROWS*(NH+NKV)*64 = 5242880
    if (idx >= ROWS * (NH + NKV) * 64) return;
    int p    = idx & 63;
    int rem  = idx >> 6;
    int head = rem % (NH + NKV);
    int row  = rem / (NH + NKV);
    int s    = row & (SEQ - 1);
    int col  = (head < NH) ? head*HD + 2*p : NH*HD + (head - NH)*HD + 2*p;
    float2 f = *(const float2*)(freqs + s*HD + 2*p);
    float* ptr = qkv + (size_t)row * QKV_N + col;
    float2 v = *(float2*)ptr;
    float n0 = v.x * f.x - v.y * f.y;
    float n1 = v.y * f.x + v.x * f.y;
    *(float2*)ptr = make_float2(n0, n1);
}

// ---------------- generic SGEMM: C[M,N] = A[M,K] * B[N,K]^T with epilogue ------
// EPI 0: C = acc ; EPI 1: C = acc + X ; EPI 2: C = silu(X) * acc
__device__ __forceinline__ float silu_f(float z) { return z / (1.0f + __expf(-z)); }

template<int EPI>
__global__ __launch_bounds__(256, 2) void sgemm_nt(
    const float* __restrict__ A, const float* __restrict__ B,
    float* __restrict__ C, const float* __restrict__ X,
    int M, int N, int K)
{
    __shared__ float As[16][128];
    __shared__ float Bs[16][128];
    int bx = blockIdx.x, by = blockIdx.y;
    int tid = threadIdx.x;
    int tx = tid & 15, ty = tid >> 4;
    const float* Ab = A + (size_t)(by * 128) * K;
    const float* Bb = B + (size_t)(bx * 128) * K;
    int lr = tid >> 2;        // 0..63
    int lc = (tid & 3) * 4;   // 0,4,8,12

    float acc[8][8];
    #pragma unroll
    for (int i = 0; i < 8; i++)
        #pragma unroll
        for (int j = 0; j < 8; j++) acc[i][j] = 0.0f;

    for (int k0 = 0; k0 < K; k0 += 16) {
        float4 a0 = *(const float4*)(Ab + (size_t)lr * K + k0 + lc);
        float4 a1 = *(const float4*)(Ab + (size_t)(lr + 64) * K + k0 + lc);
        float4 b0 = *(const float4*)(Bb + (size_t)lr * K + k0 + lc);
        float4 b1 = *(const float4*)(Bb + (size_t)(lr + 64) * K + k0 + lc);
        __syncthreads();
        As[lc+0][lr] = a0.x; As[lc+1][lr] = a0.y; As[lc+2][lr] = a0.z; As[lc+3][lr] = a0.w;
        As[lc+0][lr+64] = a1.x; As[lc+1][lr+64] = a1.y; As[lc+2][lr+64] = a1.z; As[lc+3][lr+64] = a1.w;
        Bs[lc+0][lr] = b0.x; Bs[lc+1][lr] = b0.y; Bs[lc+2][lr] = b0.z; Bs[lc+3][lr] = b0.w;
        Bs[lc+0][lr+64] = b1.x; Bs[lc+1][lr+64] = b1.y; Bs[lc+2][lr+64] = b1.z; Bs[lc+3][lr+64] = b1.w;
        __syncthreads();
        #pragma unroll
        for (int kk = 0; kk < 16; kk++) {
            float4 ra0 = *(float4*)&As[kk][ty*4];
            float4 ra1 = *(float4*)&As[kk][64 + ty*4];
            float4 rb0 = *(float4*)&Bs[kk][tx*4];
            float4 rb1 = *(float4*)&Bs[kk][64 + tx*4];
            float a[8] = {ra0.x, ra0.y, ra0.z, ra0.w, ra1.x, ra1.y, ra1.z, ra1.w};
            float b[8] = {rb0.x, rb0.y, rb0.z, rb0.w, rb1.x, rb1.y, rb1.z, rb1.w};
            #pragma unroll
            for (int i = 0; i < 8; i++)
                #pragma unroll
                for (int j = 0; j < 8; j++)
                    acc[i][j] = fmaf(a[i], b[j], acc[i][j]);
        }
    }

    #pragma unroll
    for (int ii = 0; ii < 2; ii++) {
        #pragma unroll
        for (int i = 0; i < 4; i++) {
            int r = by*128 + ii*64 + ty*4 + i;
            size_t rowoff = (size_t)r * N + bx*128;
            #pragma unroll
            for (int jj = 0; jj < 2; jj++) {
                int c0 = jj*64 + tx*4;
                float4 v;
                v.x = acc[ii*4+i][jj*4+0];
                v.y = acc[ii*4+i][jj*4+1];
                v.z = acc[ii*4+i][jj*4+2];
                v.w = acc[ii*4+i][jj*4+3];
                if (EPI == 1) {
                    float4 xo = *(const float4*)(X + rowoff + c0);
                    v.x += xo.x; v.y += xo.y; v.z += xo.z; v.w += xo.w;
                } else if (EPI == 2) {
                    float4 z = *(const float4*)(X + rowoff + c0);
                    v.x *= silu_f(z.x); v.y *= silu_f(z.y);
                    v.z *= silu_f(z.z); v.w *= silu_f(z.w);
                }
                *(float4*)(C + rowoff + c0) = v;
            }
        }
    }
}

// ---------------- flash attention (fp32, causal, GQA) --------------------------
// grid: (SEQ/64, NH, BATCH), 256 threads, dynamic smem 112KB
#define ATTN_SMEM ((128*64 + 128*64 + 64*128 + 64*64) * 4)

__global__ __launch_bounds__(256) void attn_kernel(
    const float* __restrict__ qkv, float* __restrict__ out)
{
    extern __shared__ float sm[];
    float* Qt = sm;                 // [128][64] transposed: Qt[d][r]
    float* Kt = sm + 128*64;        // [128][64] transposed: Kt[d][c]
    float* Vs = Kt + 128*64;        // [64][128] row-major
    float* Ps = Vs + 64*128;        // [64][64]

    int q0 = blockIdx.x * 64;
    int h  = blockIdx.y;
    int b  = blockIdx.z;
    int kvh = h >> 2;
    int tid = threadIdx.x;
    int tx = tid & 15, ty = tid >> 4;
    const float scale = rsqrtf((float)EMBED);

    // load Q tile (transposed into smem)
    #pragma unroll
    for (int i = 0; i < 8; i++) {
        int e = tid + i * 256;          // 0..2047
        int r = e >> 5;                 // 0..63
        int c4 = (e & 31) * 4;          // 0..124
        float4 v = *(const float4*)(qkv + (size_t)(b*SEQ + q0 + r) * QKV_N + h*HD + c4);
        Qt[(c4+0)*64 + r] = v.x;
        Qt[(c4+1)*64 + r] = v.y;
        Qt[(c4+2)*64 + r] = v.z;
        Qt[(c4+3)*64 + r] = v.w;
    }

    float m_i[4], l_i[4], O[4][8];
    #pragma unroll
    for (int i = 0; i < 4; i++) {
        m_i[i] = -1e30f; l_i[i] = 0.0f;
        #pragma unroll
        for (int j = 0; j < 8; j++) O[i][j] = 0.0f;
    }

    int ktiles = blockIdx.x + 1;
    for (int kt = 0; kt < ktiles; kt++) {
        int k0 = kt * 64;
        __syncthreads();  // guard Kt/Vs/Ps reuse from previous iteration
        #pragma unroll
        for (int i = 0; i < 8; i++) {
            int e = tid + i * 256;
            int r = e >> 5;
            int c4 = (e & 31) * 4;
            size_t base = (size_t)(b*SEQ + k0 + r) * QKV_N;
            float4 kv4 = *(const float4*)(qkv + base + NH*HD + kvh*HD + c4);
            Kt[(c4+0)*64 + r] = kv4.x;
            Kt[(c4+1)*64 + r] = kv4.y;
            Kt[(c4+2)*64 + r] = kv4.z;
            Kt[(c4+3)*64 + r] = kv4.w;
            float4 vv4 = *(const float4*)(qkv + base + (NH+NKV)*HD + kvh*HD + c4);
            *(float4*)(Vs + r*128 + c4) = vv4;
        }
        __syncthreads();

        // scores: 4 rows (ty*4..) x 4 cols (tx*4..)
        float s[4][4];
        #pragma unroll
        for (int i = 0; i < 4; i++)
            #pragma unroll
            for (int j = 0; j < 4; j++) s[i][j] = 0.0f;
        for (int d = 0; d < 128; d++) {
            float4 qa = *(float4*)(Qt + d*64 + ty*4);
            float4 kb = *(float4*)(Kt + d*64 + tx*4);
            float qr[4] = {qa.x, qa.y, qa.z, qa.w};
            float kr[4] = {kb.x, kb.y, kb.z, kb.w};
            #pragma unroll
            for (int i = 0; i < 4; i++)
                #pragma unroll
                for (int j = 0; j < 4; j++)
                    s[i][j] = fmaf(qr[i], kr[j], s[i][j]);
        }
        bool diag = (kt == blockIdx.x);
        #pragma unroll
        for (int i = 0; i < 4; i++) {
            int rg = q0 + ty*4 + i;
            #pragma unroll
            for (int j = 0; j < 4; j++) {
                s[i][j] *= scale;
                if (diag && (k0 + tx*4 + j > rg)) s[i][j] = -1e30f;
            }
        }
        // online softmax per row (16-lane groups share a row set)
        #pragma unroll
        for (int i = 0; i < 4; i++) {
            float mt = fmaxf(fmaxf(s[i][0], s[i][1]), fmaxf(s[i][2], s[i][3]));
            #pragma unroll
            for (int m = 8; m; m >>= 1) mt = fmaxf(mt, __shfl_xor_sync(0xffffffffu, mt, m));
            float mn = fmaxf(m_i[i], mt);
            float corr = __expf(m_i[i] - mn);
            float lad = 0.0f;
            #pragma unroll
            for (int j = 0; j < 4; j++) {
                float p = __expf(s[i][j] - mn);
                Ps[(ty*4 + i)*64 + tx*4 + j] = p;
                lad += p;
            }
            #pragma unroll
            for (int m = 8; m; m >>= 1) lad += __shfl_xor_sync(0xffffffffu, lad, m);
            l_i[i] = l_i[i] * corr + lad;
            m_i[i] = mn;
            #pragma unroll
            for (int j = 0; j < 8; j++) O[i][j] *= corr;
        }
        __syncthreads();
        // O += P @ V  (rows ty*4.., dims tx*8..)
        for (int c = 0; c < 64; c++) {
            float4 v0 = *(float4*)(Vs + c*128 + tx*8);
            float4 v1 = *(float4*)(Vs + c*128 + tx*8 + 4);
            #pragma unroll
            for (int i = 0; i < 4; i++) {
                float p = Ps[(ty*4 + i)*64 + c];
                O[i][0] = fmaf(p, v0.x, O[i][0]);
                O[i][1] = fmaf(p, v0.y, O[i][1]);
                O[i][2] = fmaf(p, v0.z, O[i][2]);
                O[i][3] = fmaf(p, v0.w, O[i][3]);
                O[i][4] = fmaf(p, v1.x, O[i][4]);
                O[i][5] = fmaf(p, v1.y, O[i][5]);
                O[i][6] = fmaf(p, v1.z, O[i][6]);
                O[i][7] = fmaf(p, v1.w, O[i][7]);
            }
        }
    }

    // write normalized output: (b, s, h*HD + d)
    #pragma unroll
    for (int i = 0; i < 4; i++) {
        float inv = 1.0f / l_i[i];
        int r = q0 + ty*4 + i;
        float* op = out + (size_t)(b*SEQ + r) * EMBED + h*HD + tx*8;
        float4 o0 = make_float4(O[i][0]*inv, O[i][1]*inv, O[i][2]*inv, O[i][3]*inv);
        float4 o1 = make_float4(O[i][4]*inv, O[i][5]*inv, O[i][6]*inv, O[i][7]*inv);
        *(float4*)op       = o0;
        *(float4*)(op + 4) = o1;
    }
}

// ---------------- launcher -----------------------------------------------------
extern "C" void kernel_launch(void* const* d_in, const int* in_sizes, int n_in,
                              void* d_out, int out_size)
{
    const float* x      = (const float*)d_in[0];
    // d_in[1] attention_mask (int32, tril causal) - semantics implemented directly
    const float* freqs  = (const float*)d_in[2];
    // d_in[3] input_pos (arange) - implicit
    const float* w_qkv  = (const float*)d_in[4];
    const float* w_fc   = (const float*)d_in[5];
    const float* w1     = (const float*)d_in[6];
    const float* w2     = (const float*)d_in[7];
    const float* w3     = (const float*)d_in[8];
    const float* attn_w = (const float*)d_in[9];
    const float* ff_w   = (const float*)d_in[10];
    float* out = (float*)d_out;

    float *norm, *qkv, *attn, *h2, *ff1, *ff2;
    cudaGetSymbolAddress((void**)&norm, g_norm);
    cudaGetSymbolAddress((void**)&qkv,  g_qkv);
    cudaGetSymbolAddress((void**)&attn, g_attn);
    cudaGetSymbolAddress((void**)&h2,   g_h2);
    cudaGetSymbolAddress((void**)&ff1,  g_ff1);
    cudaGetSymbolAddress((void**)&ff2,  g_ff2);

    cudaFuncSetAttribute((const void*)attn_kernel,
                         cudaFuncAttributeMaxDynamicSharedMemorySize, ATTN_SMEM);

    // 1) h = rmsnorm(x) * attn_norm_w
    rmsnorm_kernel<<<ROWS, 256>>>(x, attn_w, norm);
    // 2) qkv = h @ w_qkv^T
    sgemm_nt<0><<<dim3(QKV_N/128, ROWS/128), 256>>>(norm, w_qkv, qkv, nullptr, ROWS, QKV_N, EMBED);
    // 3) RoPE on q,k
    rope_kernel<<<(ROWS*(NH+NKV)*64 + 255)/256, 256>>>(qkv, freqs);
    // 4) causal flash attention
    attn_kernel<<<dim3(SEQ/64, NH, BATCH), 256, ATTN_SMEM>>>(qkv, attn);
    // 5) h2 = x + attn @ w_fc^T
    sgemm_nt<1><<<dim3(EMBED/128, ROWS/128), 256>>>(attn, w_fc, h2, x, ROWS, EMBED, EMBED);
    // 6) g = rmsnorm(h2) * ff_norm_w
    rmsnorm_kernel<<<ROWS, 256>>>(h2, ff_w, norm);
    // 7) a1 = g @ w1^T
    sgemm_nt<0><<<dim3(FF/128, ROWS/128), 256>>>(norm, w1, ff1, nullptr, ROWS, FF, EMBED);
    // 8) ff = silu(a1) * (g @ w2^T)
    sgemm_nt<2><<<dim3(FF/128, ROWS/128), 256>>>(norm, w2, ff2, ff1, ROWS, FF, EMBED);
    // 9) out = h2 + ff @ w3^T
    sgemm_nt<1><<<dim3(EMBED/128, ROWS/128), 256>>>(ff2, w3, out, h2, ROWS, EMBED, FF);
}

// round 4
// speedup vs baseline: 1.8787x; 1.8787x over previous
#include <cuda_runtime.h>
#include <cuda_bf16.h>
#include <math.h>
#include <cstdint>

// Problem constants
#define BATCH 2
#define SEQ   2048
#define EMBED 2048
#define NH    16
#define NKV   4
#define HD    128
#define FF    5632
#define ROWS  (BATCH*SEQ)          // 4096
#define QKV_N ((NH + 2*NKV)*HD)    // 3072

// ================= scratch (static device globals) =============================
__device__ float g_qkv [ROWS*QKV_N];
__device__ float g_attn[ROWS*EMBED];
__device__ float g_h2  [ROWS*EMBED];
__device__ float g_ff1 [ROWS*FF];
__device__ __nv_bfloat16 g_nhi[ROWS*EMBED], g_nlo[ROWS*EMBED];
__device__ __nv_bfloat16 g_ahi[ROWS*EMBED], g_alo[ROWS*EMBED];
__device__ __nv_bfloat16 g_fhi[ROWS*FF],    g_flo[ROWS*FF];
__device__ __nv_bfloat16 g_wqkv_h[QKV_N*EMBED], g_wqkv_l[QKV_N*EMBED];
__device__ __nv_bfloat16 g_wfc_h[EMBED*EMBED],  g_wfc_l[EMBED*EMBED];
__device__ __nv_bfloat16 g_w1_h[FF*EMBED],      g_w1_l[FF*EMBED];
__device__ __nv_bfloat16 g_w2_h[FF*EMBED],      g_w2_l[FF*EMBED];
__device__ __nv_bfloat16 g_w3_h[EMBED*FF],      g_w3_l[EMBED*FF];

// ================= elementwise helpers =========================================
__device__ __forceinline__ float silu_f(float z) { return z / (1.0f + __expf(-z)); }

__device__ __forceinline__ void store_hl4(__nv_bfloat16* __restrict__ hi,
                                          __nv_bfloat16* __restrict__ lo,
                                          size_t idx, float a, float b, float c, float d)
{
    __nv_bfloat16 h0 = __float2bfloat16(a), h1 = __float2bfloat16(b);
    __nv_bfloat16 h2 = __float2bfloat16(c), h3 = __float2bfloat16(d);
    __nv_bfloat16 l0 = __float2bfloat16(a - __bfloat162float(h0));
    __nv_bfloat16 l1 = __float2bfloat16(b - __bfloat162float(h1));
    __nv_bfloat16 l2 = __float2bfloat16(c - __bfloat162float(h2));
    __nv_bfloat16 l3 = __float2bfloat16(d - __bfloat162float(h3));
    __nv_bfloat162 p;
    p.x = h0; p.y = h1; *(__nv_bfloat162*)(hi + idx)     = p;
    p.x = h2; p.y = h3; *(__nv_bfloat162*)(hi + idx + 2) = p;
    p.x = l0; p.y = l1; *(__nv_bfloat162*)(lo + idx)     = p;
    p.x = l2; p.y = l3; *(__nv_bfloat162*)(lo + idx + 2) = p;
}

__device__ __forceinline__ void store_hl2(__nv_bfloat16* __restrict__ hi,
                                          __nv_bfloat16* __restrict__ lo,
                                          size_t idx, float a, float b)
{
    __nv_bfloat16 h0 = __float2bfloat16(a), h1 = __float2bfloat16(b);
    __nv_bfloat16 l0 = __float2bfloat16(a - __bfloat162float(h0));
    __nv_bfloat16 l1 = __float2bfloat16(b - __bfloat162float(h1));
    __nv_bfloat162 p;
    p.x = h0; p.y = h1; *(__nv_bfloat162*)(hi + idx) = p;
    p.x = l0; p.y = l1; *(__nv_bfloat162*)(lo + idx) = p;
}

// fp32 -> (hi, lo) bf16 split
__global__ __launch_bounds__(256) void cvt_hl(
    const float* __restrict__ src, __nv_bfloat16* __restrict__ hi,
    __nv_bfloat16* __restrict__ lo, int n4)
{
    int i = blockIdx.x * 256 + threadIdx.x;
    if (i >= n4) return;
    float4 v = ((const float4*)src)[i];
    store_hl4(hi, lo, (size_t)i * 4, v.x, v.y, v.z, v.w);
}

// rmsnorm with hi/lo bf16 output
__global__ __launch_bounds__(256) void rmsnorm_hl(
    const float* __restrict__ x, const float* __restrict__ w,
    __nv_bfloat16* __restrict__ hi, __nv_bfloat16* __restrict__ lo)
{
    int row = blockIdx.x;
    const float4* xr = (const float4*)(x + (size_t)row * EMBED);
    int t = threadIdx.x;
    float4 v0 = xr[t];
    float4 v1 = xr[t + 256];
    float ss = v0.x*v0.x + v0.y*v0.y + v0.z*v0.z + v0.w*v0.w
             + v1.x*v1.x + v1.y*v1.y + v1.z*v1.z + v1.w*v1.w;
    #pragma unroll
    for (int m = 16; m; m >>= 1) ss += __shfl_xor_sync(0xffffffffu, ss, m);
    __shared__ float red[8];
    if ((t & 31) == 0) red[t >> 5] = ss;
    __syncthreads();
    float tot = red[0]+red[1]+red[2]+red[3]+red[4]+red[5]+red[6]+red[7];
    float r = rsqrtf(tot * (1.0f/EMBED) + 1e-5f);
    const float4* wr = (const float4*)w;
    float4 w0 = wr[t], w1 = wr[t + 256];
    size_t base = (size_t)row * EMBED;
    store_hl4(hi, lo, base + t*4,        v0.x*r*w0.x, v0.y*r*w0.y, v0.z*r*w0.z, v0.w*r*w0.w);
    store_hl4(hi, lo, base + 1024 + t*4, v1.x*r*w1.x, v1.y*r*w1.y, v1.z*r*w1.z, v1.w*r*w1.w);
}

// ---------------- RoPE (in-place on qkv buffer, q + k heads) -------------------
__global__ __launch_bounds__(256) void rope_kernel(
    float* __restrict__ qkv, const float* __restrict__ freqs)
{
    int idx = blockIdx.x * 256 + threadIdx.x;
    if (idx >= ROWS * (NH + NKV) * 64) return;
    int p    = idx & 63;
    int rem  = idx >> 6;
    int head = rem % (NH + NKV);
    int row  = rem / (NH + NKV);
    int s    = row & (SEQ - 1);
    int col  = (head < NH) ? head*HD + 2*p : NH*HD + (head - NH)*HD + 2*p;
    float2 f = *(const float2*)(freqs + s*HD + 2*p);
    float* ptr = qkv + (size_t)row * QKV_N + col;
    float2 v = *(float2*)ptr;
    float n0 = v.x * f.x - v.y * f.y;
    float n1 = v.y * f.x + v.x * f.y;
    *(float2*)ptr = make_float2(n0, n1);
}

// ================= HMMA bf16x3 GEMM ============================================
// C[M,N] = A[M,K] @ B[N,K]^T with A,B as (hi,lo) bf16 pairs; 3-product compensation.
// EPI 0: Cf = acc ; EPI 1: Cf = acc + X ; EPI 3: (Chi,Clo) = split(acc * silu(X))
//
// CTA tile 128x128, BK=32, 8 warps in 2(m) x 4(n), warp tile 64x32.
// SMEM rows padded to 40 bf16 (80 B) -> ldmatrix bank-group (5r+c) mod 8 is a
// permutation over 8 rows => conflict-free.

#define BKC      32                    // K per chunk (bf16 elems)
#define RS       40                    // padded row stride (bf16 elems), 80 B
#define TILE_PB  (128*RS*2)            // 10240 B per 128xBKC tile
#define STAGE_B  (4*TILE_PB)           // Ahi,Alo,Bhi,Blo
#define NSTAGE   4
#define GEMM_SMEM (NSTAGE*STAGE_B)     // 163840

__device__ __forceinline__ uint32_t smem_u32(const void* p) {
    uint32_t a;
    asm("{ .reg .u64 t; cvta.to.shared.u64 t, %1; cvt.u32.u64 %0, t; }" : "=r"(a) : "l"(p));
    return a;
}

__device__ __forceinline__ void ldsm_x4(uint32_t (&r)[4], uint32_t addr) {
    asm volatile("ldmatrix.sync.aligned.m8n8.x4.shared.b16 {%0,%1,%2,%3}, [%4];"
                 : "=r"(r[0]), "=r"(r[1]), "=r"(r[2]), "=r"(r[3]) : "r"(addr));
}

__device__ __forceinline__ void mma_bf16(float (&d)[4], const uint32_t (&a)[4],
                                         uint32_t b0, uint32_t b1) {
    asm volatile(
        "mma.sync.aligned.m16n8k16.row.col.f32.bf16.bf16.f32 "
        "{%0,%1,%2,%3}, {%4,%5,%6,%7}, {%8,%9}, {%0,%1,%2,%3};"
        : "+f"(d[0]), "+f"(d[1]), "+f"(d[2]), "+f"(d[3])
        : "r"(a[0]), "r"(a[1]), "r"(a[2]), "r"(a[3]), "r"(b0), "r"(b1));
}

__device__ __forceinline__ void load_stage(
    uint32_t sb, int stage, int chunk, int tid,
    const __nv_bfloat16* __restrict__ A0, const __nv_bfloat16* __restrict__ A1,
    const __nv_bfloat16* __restrict__ B0, const __nv_bfloat16* __restrict__ B1, int K)
{
    const __nv_bfloat16* mats[4] = {A0, A1, B0, B1};
    uint32_t stage_base = sb + (uint32_t)stage * STAGE_B;
    #pragma unroll
    for (int m = 0; m < 4; m++) {
        const __nv_bfloat16* gp = mats[m] + chunk * BKC;
        uint32_t tb = stage_base + m * TILE_PB;
        #pragma unroll
        for (int it = 0; it < 2; it++) {
            int ch = it * 256 + tid;        // 0..511
            int r  = ch >> 2;               // 0..127
            int cc = ch & 3;                // 16B chunk within row
            uint32_t so = tb + (uint32_t)(r * (RS*2) + cc * 16);
            const void* ga = gp + (size_t)r * K + cc * 8;
            asm volatile("cp.async.cg.shared.global [%0], [%1], 16;\n" :: "r"(so), "l"(ga));
        }
    }
}

template<int EPI>
__global__ __launch_bounds__(256, 1) void hmma_gemm(
    const __nv_bfloat16* __restrict__ Ahi, const __nv_bfloat16* __restrict__ Alo,
    const __nv_bfloat16* __restrict__ Bhi, const __nv_bfloat16* __restrict__ Blo,
    float* __restrict__ Cf, const float* __restrict__ X,
    __nv_bfloat16* __restrict__ Chi, __nv_bfloat16* __restrict__ Clo,
    int M, int N, int K)
{
    extern __shared__ char smem[];
    uint32_t sb = smem_u32(smem);
    const int tid  = threadIdx.x;
    const int wid  = tid >> 5;
    const int lane = tid & 31;
    const int bx = blockIdx.x, by = blockIdx.y;
    const int wm = (wid >> 2) * 64;   // 0 or 64
    const int wn = (wid & 3) * 32;    // 0,32,64,96

    const __nv_bfloat16* A0 = Ahi + (size_t)by * 128 * K;
    const __nv_bfloat16* A1 = Alo + (size_t)by * 128 * K;
    const __nv_bfloat16* B0 = Bhi + (size_t)bx * 128 * K;
    const __nv_bfloat16* B1 = Blo + (size_t)bx * 128 * K;

    float d[4][4][4];  // [mi][ni][reg]
    #pragma unroll
    for (int i = 0; i < 4; i++)
        #pragma unroll
        for (int j = 0; j < 4; j++)
            #pragma unroll
            for (int r = 0; r < 4; r++) d[i][j][r] = 0.0f;

    // ldmatrix per-lane address components (byte offsets within a tile)
    const int a_row = lane & 15;                       // + wm + mi*16
    const int a_cb  = (lane >> 4) * 16;                // k-chunk byte
    const int b_row = (lane & 7) | ((lane >> 1) & 8);  // + wn + bi*16
    const int b_cb  = ((lane >> 3) & 1) * 16;

    const int NC = K / BKC;

    #pragma unroll
    for (int s = 0; s < NSTAGE - 1; s++) {
        load_stage(sb, s, s, tid, A0, A1, B0, B1, K);
        asm volatile("cp.async.commit_group;\n" ::: "memory");
    }

    for (int c = 0; c < NC; c++) {
        asm volatile("cp.async.wait_group %0;\n" :: "n"(NSTAGE - 2) : "memory");
        __syncthreads();
        if (c + NSTAGE - 1 < NC)
            load_stage(sb, (c + NSTAGE - 1) & (NSTAGE - 1), c + NSTAGE - 1, tid, A0, A1, B0, B1, K);
        asm volatile("cp.async.commit_group;\n" ::: "memory");

        uint32_t st = sb + (uint32_t)(c & (NSTAGE - 1)) * STAGE_B;
        uint32_t ah_b = st;
        uint32_t al_b = st + TILE_PB;
        uint32_t bh_b = st + 2*TILE_PB;
        uint32_t bl_b = st + 3*TILE_PB;

        #pragma unroll
        for (int ks = 0; ks < 2; ks++) {
            uint32_t ah[4][4], al[4][4], bh[2][4], bl[2][4];
            #pragma unroll
            for (int mi = 0; mi < 4; mi++) {
                uint32_t off = (uint32_t)((wm + mi*16 + a_row) * (RS*2) + a_cb + ks*32);
                ldsm_x4(ah[mi], ah_b + off);
                ldsm_x4(al[mi], al_b + off);
            }
            #pragma unroll
            for (int bi = 0; bi < 2; bi++) {
                uint32_t off = (uint32_t)((wn + bi*16 + b_row) * (RS*2) + b_cb + ks*32);
                ldsm_x4(bh[bi], bh_b + off);
                ldsm_x4(bl[bi], bl_b + off);
            }
            #pragma unroll
            for (int mi = 0; mi < 4; mi++) {
                #pragma unroll
                for (int ni = 0; ni < 4; ni++) {
                    int bi = ni >> 1, hf = (ni & 1) * 2;
                    mma_bf16(d[mi][ni], ah[mi], bh[bi][hf], bh[bi][hf+1]);   // hi*hi
                    mma_bf16(d[mi][ni], ah[mi], bl[bi][hf], bl[bi][hf+1]);   // hi*lo
                    mma_bf16(d[mi][ni], al[mi], bh[bi][hf], bh[bi][hf+1]);   // lo*hi
                }
            }
        }
    }

    // -------- epilogue --------
    const int q  = lane >> 2;
    const int tq = lane & 3;
    #pragma unroll
    for (int mi = 0; mi < 4; mi++) {
        int row0 = by*128 + wm + mi*16 + q;
        #pragma unroll
        for (int ni = 0; ni < 4; ni++) {
            int col = bx*128 + wn + ni*8 + tq*2;
            size_t off0 = (size_t)row0 * N + col;
            size_t off1 = off0 + (size_t)8 * N;
            float v0 = d[mi][ni][0], v1 = d[mi][ni][1];
            float v2 = d[mi][ni][2], v3 = d[mi][ni][3];
            if (EPI == 0) {
                *(float2*)(Cf + off0) = make_float2(v0, v1);
                *(float2*)(Cf + off1) = make_float2(v2, v3);
            } else if (EPI == 1) {
                float2 x0 = *(const float2*)(X + off0);
                float2 x1 = *(const float2*)(X + off1);
                *(float2*)(Cf + off0) = make_float2(v0 + x0.x, v1 + x0.y);
                *(float2*)(Cf + off1) = make_float2(v2 + x1.x, v3 + x1.y);
            } else {  // EPI 3
                float2 x0 = *(const float2*)(X + off0);
                float2 x1 = *(const float2*)(X + off1);
                store_hl2(Chi, Clo, off0, v0 * silu_f(x0.x), v1 * silu_f(x0.y));
                store_hl2(Chi, Clo, off1, v2 * silu_f(x1.x), v3 * silu_f(x1.y));
            }
        }
    }
}

// ================= flash attention (fp32, causal, GQA) =========================
#define ATTN_SMEM ((128*64 + 128*64 + 64*128 + 64*64) * 4)

__global__ __launch_bounds__(256) void attn_kernel(
    const float* __restrict__ qkv, float* __restrict__ out)
{
    extern __shared__ float sm[];
    float* Qt = sm;                 // [128][64] transposed
    float* Kt = sm + 128*64;        // [128][64] transposed
    float* Vs = Kt + 128*64;        // [64][128]
    float* Ps = Vs + 64*128;        // [64][64]

    int q0 = blockIdx.x * 64;
    int h  = blockIdx.y;
    int b  = blockIdx.z;
    int kvh = h >> 2;
    int tid = threadIdx.x;
    int tx = tid & 15, ty = tid >> 4;
    const float scale = rsqrtf((float)EMBED);

    #pragma unroll
    for (int i = 0; i < 8; i++) {
        int e = tid + i * 256;
        int r = e >> 5;
        int c4 = (e & 31) * 4;
        float4 v = *(const float4*)(qkv + (size_t)(b*SEQ + q0 + r) * QKV_N + h*HD + c4);
        Qt[(c4+0)*64 + r] = v.x;
        Qt[(c4+1)*64 + r] = v.y;
        Qt[(c4+2)*64 + r] = v.z;
        Qt[(c4+3)*64 + r] = v.w;
    }

    float m_i[4], l_i[4], O[4][8];
    #pragma unroll
    for (int i = 0; i < 4; i++) {
        m_i[i] = -1e30f; l_i[i] = 0.0f;
        #pragma unroll
        for (int j = 0; j < 8; j++) O[i][j] = 0.0f;
    }

    int ktiles = blockIdx.x + 1;
    for (int kt = 0; kt < ktiles; kt++) {
        int k0 = kt * 64;
        __syncthreads();
        #pragma unroll
        for (int i = 0; i < 8; i++) {
            int e = tid + i * 256;
            int r = e >> 5;
            int c4 = (e & 31) * 4;
            size_t base = (size_t)(b*SEQ + k0 + r) * QKV_N;
            float4 kv4 = *(const float4*)(qkv + base + NH*HD + kvh*HD + c4);
            Kt[(c4+0)*64 + r] = kv4.x;
            Kt[(c4+1)*64 + r] = kv4.y;
            Kt[(c4+2)*64 + r] = kv4.z;
            Kt[(c4+3)*64 + r] = kv4.w;
            float4 vv4 = *(const float4*)(qkv + base + (NH+NKV)*HD + kvh*HD + c4);
            *(float4*)(Vs + r*128 + c4) = vv4;
        }
        __syncthreads();

        float s[4][4];
        #pragma unroll
        for (int i = 0; i < 4; i++)
            #pragma unroll
            for (int j = 0; j < 4; j++) s[i][j] = 0.0f;
        for (int dgl = 0; dgl < 128; dgl++) {
            float4 qa = *(float4*)(Qt + dgl*64 + ty*4);
            float4 kb = *(float4*)(Kt + dgl*64 + tx*4);
            float qr[4] = {qa.x, qa.y, qa.z, qa.w};
            float kr[4] = {kb.x, kb.y, kb.z, kb.w};
            #pragma unroll
            for (int i = 0; i < 4; i++)
                #pragma unroll
                for (int j = 0; j < 4; j++)
                    s[i][j] = fmaf(qr[i], kr[j], s[i][j]);
        }
        bool diag = (kt == blockIdx.x);
        #pragma unroll
        for (int i = 0; i < 4; i++) {
            int rg = q0 + ty*4 + i;
            #pragma unroll
            for (int j = 0; j < 4; j++) {
                s[i][j] *= scale;
                if (diag && (k0 + tx*4 + j > rg)) s[i][j] = -1e30f;
            }
        }
        #pragma unroll
        for (int i = 0; i < 4; i++) {
            float mt = fmaxf(fmaxf(s[i][0], s[i][1]), fmaxf(s[i][2], s[i][3]));
            #pragma unroll
            for (int m = 8; m; m >>= 1) mt = fmaxf(mt, __shfl_xor_sync(0xffffffffu, mt, m));
            float mn = fmaxf(m_i[i], mt);
            float corr = __expf(m_i[i] - mn);
            float lad = 0.0f;
            #pragma unroll
            for (int j = 0; j < 4; j++) {
                float p = __expf(s[i][j] - mn);
                Ps[(ty*4 + i)*64 + tx*4 + j] = p;
                lad += p;
            }
            #pragma unroll
            for (int m = 8; m; m >>= 1) lad += __shfl_xor_sync(0xffffffffu, lad, m);
            l_i[i] = l_i[i] * corr + lad;
            m_i[i] = mn;
            #pragma unroll
            for (int j = 0; j < 8; j++) O[i][j] *= corr;
        }
        __syncthreads();
        for (int c = 0; c < 64; c++) {
            float4 v0 = *(float4*)(Vs + c*128 + tx*8);
            float4 v1 = *(float4*)(Vs + c*128 + tx*8 + 4);
            #pragma unroll
            for (int i = 0; i < 4; i++) {
                float p = Ps[(ty*4 + i)*64 + c];
                O[i][0] = fmaf(p, v0.x, O[i][0]);
                O[i][1] = fmaf(p, v0.y, O[i][1]);
                O[i][2] = fmaf(p, v0.z, O[i][2]);
                O[i][3] = fmaf(p, v0.w, O[i][3]);
                O[i][4] = fmaf(p, v1.x, O[i][4]);
                O[i][5] = fmaf(p, v1.y, O[i][5]);
                O[i][6] = fmaf(p, v1.z, O[i][6]);
                O[i][7] = fmaf(p, v1.w, O[i][7]);
            }
        }
    }

    #pragma unroll
    for (int i = 0; i < 4; i++) {
        float inv = 1.0f / l_i[i];
        int r = q0 + ty*4 + i;
        float* op = out + (size_t)(b*SEQ + r) * EMBED + h*HD + tx*8;
        float4 o0 = make_float4(O[i][0]*inv, O[i][1]*inv, O[i][2]*inv, O[i][3]*inv);
        float4 o1 = make_float4(O[i][4]*inv, O[i][5]*inv, O[i][6]*inv, O[i][7]*inv);
        *(float4*)op       = o0;
        *(float4*)(op + 4) = o1;
    }
}

// ================= launcher ====================================================
extern "C" void kernel_launch(void* const* d_in, const int* in_sizes, int n_in,
                              void* d_out, int out_size)
{
    const float* x      = (const float*)d_in[0];
    const float* freqs  = (const float*)d_in[2];
    const float* w_qkv  = (const float*)d_in[4];
    const float* w_fc   = (const float*)d_in[5];
    const float* w1     = (const float*)d_in[6];
    const float* w2     = (const float*)d_in[7];
    const float* w3     = (const float*)d_in[8];
    const float* attn_w = (const float*)d_in[9];
    const float* ff_w   = (const float*)d_in[10];
    float* out = (float*)d_out;

    float *qkv, *attn, *h2, *ff1;
    __nv_bfloat16 *nhi, *nlo, *ahi, *alo, *fhi, *flo;
    __nv_bfloat16 *wqh, *wql, *wfh, *wfl, *w1h, *w1l, *w2h, *w2l, *w3h, *w3l;
    cudaGetSymbolAddress((void**)&qkv,  g_qkv);
    cudaGetSymbolAddress((void**)&attn, g_attn);
    cudaGetSymbolAddress((void**)&h2,   g_h2);
    cudaGetSymbolAddress((void**)&ff1,  g_ff1);
    cudaGetSymbolAddress((void**)&nhi,  g_nhi);  cudaGetSymbolAddress((void**)&nlo, g_nlo);
    cudaGetSymbolAddress((void**)&ahi,  g_ahi);  cudaGetSymbolAddress((void**)&alo, g_alo);
    cudaGetSymbolAddress((void**)&fhi,  g_fhi);  cudaGetSymbolAddress((void**)&flo, g_flo);
    cudaGetSymbolAddress((void**)&wqh,  g_wqkv_h); cudaGetSymbolAddress((void**)&wql, g_wqkv_l);
    cudaGetSymbolAddress((void**)&wfh,  g_wfc_h);  cudaGetSymbolAddress((void**)&wfl, g_wfc_l);
    cudaGetSymbolAddress((void**)&w1h,  g_w1_h);   cudaGetSymbolAddress((void**)&w1l, g_w1_l);
    cudaGetSymbolAddress((void**)&w2h,  g_w2_h);   cudaGetSymbolAddress((void**)&w2l, g_w2_l);
    cudaGetSymbolAddress((void**)&w3h,  g_w3_h);   cudaGetSymbolAddress((void**)&w3l, g_w3_l);

    cudaFuncSetAttribute((const void*)attn_kernel,
                         cudaFuncAttributeMaxDynamicSharedMemorySize, ATTN_SMEM);
    cudaFuncSetAttribute((const void*)hmma_gemm<0>,
                         cudaFuncAttributeMaxDynamicSharedMemorySize, GEMM_SMEM);
    cudaFuncSetAttribute((const void*)hmma_gemm<1>,
                         cudaFuncAttributeMaxDynamicSharedMemorySize, GEMM_SMEM);
    cudaFuncSetAttribute((const void*)hmma_gemm<3>,
                         cudaFuncAttributeMaxDynamicSharedMemorySize, GEMM_SMEM);

    // weight hi/lo conversion
    cvt_hl<<<(QKV_N*EMBED/4 + 255)/256, 256>>>(w_qkv, wqh, wql, QKV_N*EMBED/4);
    cvt_hl<<<(EMBED*EMBED/4 + 255)/256, 256>>>(w_fc,  wfh, wfl, EMBED*EMBED/4);
    cvt_hl<<<(FF*EMBED/4 + 255)/256, 256>>>(w1, w1h, w1l, FF*EMBED/4);
    cvt_hl<<<(FF*EMBED/4 + 255)/256, 256>>>(w2, w2h, w2l, FF*EMBED/4);
    cvt_hl<<<(EMBED*FF/4 + 255)/256, 256>>>(w3, w3h, w3l, EMBED*FF/4);

    // 1) g = rmsnorm(x) -> hi/lo
    rmsnorm_hl<<<ROWS, 256>>>(x, attn_w, nhi, nlo);
    // 2) qkv = g @ w_qkv^T (fp32 out)
    hmma_gemm<0><<<dim3(QKV_N/128, ROWS/128), 256, GEMM_SMEM>>>(
        nhi, nlo, wqh, wql, qkv, nullptr, nullptr, nullptr, ROWS, QKV_N, EMBED);
    // 3) RoPE
    rope_kernel<<<(ROWS*(NH+NKV)*64 + 255)/256, 256>>>(qkv, freqs);
    // 4) attention (fp32)
    attn_kernel<<<dim3(SEQ/64, NH, BATCH), 256, ATTN_SMEM>>>(qkv, attn);
    // 5) attn -> hi/lo
    cvt_hl<<<(ROWS*EMBED/4 + 255)/256, 256>>>(attn, ahi, alo, ROWS*EMBED/4);
    // 6) h2 = x + attn @ w_fc^T
    hmma_gemm<1><<<dim3(EMBED/128, ROWS/128), 256, GEMM_SMEM>>>(
        ahi, alo, wfh, wfl, h2, x, nullptr, nullptr, ROWS, EMBED, EMBED);
    // 7) g2 = rmsnorm(h2) -> hi/lo
    rmsnorm_hl<<<ROWS, 256>>>(h2, ff_w, nhi, nlo);
    // 8) ff1 = g2 @ w1^T (fp32)
    hmma_gemm<0><<<dim3(FF/128, ROWS/128), 256, GEMM_SMEM>>>(
        nhi, nlo, w1h, w1l, ff1, nullptr, nullptr, nullptr, ROWS, FF, EMBED);
    // 9) ff = silu(ff1) * (g2 @ w2^T) -> hi/lo
    hmma_gemm<3><<<dim3(FF/128, ROWS/128), 256, GEMM_SMEM>>>(
        nhi, nlo, w2h, w2l, nullptr, ff1, fhi, flo, ROWS, FF, EMBED);
    // 10) out = h2 + ff @ w3^T
    hmma_gemm<1><<<dim3(EMBED/128, ROWS/128), 256, GEMM_SMEM>>>(
        fhi, flo, w3h, w3l, out, h2, nullptr, nullptr, ROWS, EMBED, FF);
}

// round 5
// speedup vs baseline: 2.0227x; 1.0766x over previous
#include <cuda_runtime.h>
#include <cuda_bf16.h>
#include <math.h>
#include <cstdint>

// Problem constants
#define BATCH 2
#define SEQ   2048
#define EMBED 2048
#define NH    16
#define NKV   4
#define HD    128
#define FF    5632
#define ROWS  (BATCH*SEQ)          // 4096
#define QKV_N ((NH + 2*NKV)*HD)    // 3072

// ================= scratch (static device globals) =============================
__device__ float g_qkv [ROWS*QKV_N];
__device__ float g_attn[ROWS*EMBED];
__device__ float g_h2  [ROWS*EMBED];
__device__ float g_ff1 [ROWS*FF];
__device__ __nv_bfloat16 g_nhi[ROWS*EMBED], g_nlo[ROWS*EMBED];
__device__ __nv_bfloat16 g_ahi[ROWS*EMBED], g_alo[ROWS*EMBED];
__device__ __nv_bfloat16 g_fhi[ROWS*FF],    g_flo[ROWS*FF];
__device__ __nv_bfloat16 g_wqkv_h[QKV_N*EMBED], g_wqkv_l[QKV_N*EMBED];
__device__ __nv_bfloat16 g_wfc_h[EMBED*EMBED],  g_wfc_l[EMBED*EMBED];
__device__ __nv_bfloat16 g_w1_h[FF*EMBED],      g_w1_l[FF*EMBED];
__device__ __nv_bfloat16 g_w2_h[FF*EMBED],      g_w2_l[FF*EMBED];
__device__ __nv_bfloat16 g_w3_h[EMBED*FF],      g_w3_l[EMBED*FF];

// ================= elementwise helpers =========================================
__device__ __forceinline__ float silu_f(float z) { return z / (1.0f + __expf(-z)); }

__device__ __forceinline__ void store_hl4(__nv_bfloat16* __restrict__ hi,
                                          __nv_bfloat16* __restrict__ lo,
                                          size_t idx, float a, float b, float c, float d)
{
    __nv_bfloat16 h0 = __float2bfloat16(a), h1 = __float2bfloat16(b);
    __nv_bfloat16 h2 = __float2bfloat16(c), h3 = __float2bfloat16(d);
    __nv_bfloat16 l0 = __float2bfloat16(a - __bfloat162float(h0));
    __nv_bfloat16 l1 = __float2bfloat16(b - __bfloat162float(h1));
    __nv_bfloat16 l2 = __float2bfloat16(c - __bfloat162float(h2));
    __nv_bfloat16 l3 = __float2bfloat16(d - __bfloat162float(h3));
    __nv_bfloat162 p;
    p.x = h0; p.y = h1; *(__nv_bfloat162*)(hi + idx)     = p;
    p.x = h2; p.y = h3; *(__nv_bfloat162*)(hi + idx + 2) = p;
    p.x = l0; p.y = l1; *(__nv_bfloat162*)(lo + idx)     = p;
    p.x = l2; p.y = l3; *(__nv_bfloat162*)(lo + idx + 2) = p;
}

__device__ __forceinline__ void store_hl2(__nv_bfloat16* __restrict__ hi,
                                          __nv_bfloat16* __restrict__ lo,
                                          size_t idx, float a, float b)
{
    __nv_bfloat16 h0 = __float2bfloat16(a), h1 = __float2bfloat16(b);
    __nv_bfloat16 l0 = __float2bfloat16(a - __bfloat162float(h0));
    __nv_bfloat16 l1 = __float2bfloat16(b - __bfloat162float(h1));
    __nv_bfloat162 p;
    p.x = h0; p.y = h1; *(__nv_bfloat162*)(hi + idx) = p;
    p.x = l0; p.y = l1; *(__nv_bfloat162*)(lo + idx) = p;
}

// fp32 -> (hi, lo) bf16 split
__global__ __launch_bounds__(256) void cvt_hl(
    const float* __restrict__ src, __nv_bfloat16* __restrict__ hi,
    __nv_bfloat16* __restrict__ lo, int n4)
{
    int i = blockIdx.x * 256 + threadIdx.x;
    if (i >= n4) return;
    float4 v = ((const float4*)src)[i];
    store_hl4(hi, lo, (size_t)i * 4, v.x, v.y, v.z, v.w);
}

// rmsnorm with hi/lo bf16 output
__global__ __launch_bounds__(256) void rmsnorm_hl(
    const float* __restrict__ x, const float* __restrict__ w,
    __nv_bfloat16* __restrict__ hi, __nv_bfloat16* __restrict__ lo)
{
    int row = blockIdx.x;
    const float4* xr = (const float4*)(x + (size_t)row * EMBED);
    int t = threadIdx.x;
    float4 v0 = xr[t];
    float4 v1 = xr[t + 256];
    float ss = v0.x*v0.x + v0.y*v0.y + v0.z*v0.z + v0.w*v0.w
             + v1.x*v1.x + v1.y*v1.y + v1.z*v1.z + v1.w*v1.w;
    #pragma unroll
    for (int m = 16; m; m >>= 1) ss += __shfl_xor_sync(0xffffffffu, ss, m);
    __shared__ float red[8];
    if ((t & 31) == 0) red[t >> 5] = ss;
    __syncthreads();
    float tot = red[0]+red[1]+red[2]+red[3]+red[4]+red[5]+red[6]+red[7];
    float r = rsqrtf(tot * (1.0f/EMBED) + 1e-5f);
    const float4* wr = (const float4*)w;
    float4 w0 = wr[t], w1 = wr[t + 256];
    size_t base = (size_t)row * EMBED;
    store_hl4(hi, lo, base + t*4,        v0.x*r*w0.x, v0.y*r*w0.y, v0.z*r*w0.z, v0.w*r*w0.w);
    store_hl4(hi, lo, base + 1024 + t*4, v1.x*r*w1.x, v1.y*r*w1.y, v1.z*r*w1.z, v1.w*r*w1.w);
}

// ---------------- RoPE (in-place on qkv buffer, q + k heads) -------------------
__global__ __launch_bounds__(256) void rope_kernel(
    float* __restrict__ qkv, const float* __restrict__ freqs)
{
    int idx = blockIdx.x * 256 + threadIdx.x;
    if (idx >= ROWS * (NH + NKV) * 64) return;
    int p    = idx & 63;
    int rem  = idx >> 6;
    int head = rem % (NH + NKV);
    int row  = rem / (NH + NKV);
    int s    = row & (SEQ - 1);
    int col  = (head < NH) ? head*HD + 2*p : NH*HD + (head - NH)*HD + 2*p;
    float2 f = *(const float2*)(freqs + s*HD + 2*p);
    float* ptr = qkv + (size_t)row * QKV_N + col;
    float2 v = *(float2*)ptr;
    float n0 = v.x * f.x - v.y * f.y;
    float n1 = v.y * f.x + v.x * f.y;
    *(float2*)ptr = make_float2(n0, n1);
}

// ================= HMMA bf16x3 GEMM ============================================
// C[M,N] = A[M,K] @ B[N,K]^T with A,B as (hi,lo) bf16 pairs; 3-product compensation.
// EPI 0: Cf = acc ; EPI 1: Cf = acc + X ; EPI 3: (Chi,Clo) = split(acc * silu(X))
//
// CTA tile 128x128, BK=32, 8 warps in 2(m) x 4(n), warp tile 64x32.
// 2-stage cp.async pipeline, 2 CTAs/SM (80KB smem each, <=128 regs).
// SMEM rows padded to 40 bf16 (80 B) -> ldmatrix conflict-free.

#define BKC      32                    // K per chunk (bf16 elems)
#define RS       40                    // padded row stride (bf16 elems), 80 B
#define TILE_PB  (128*RS*2)            // 10240 B per 128xBKC tile
#define STAGE_B  (4*TILE_PB)           // Ahi,Alo,Bhi,Blo
#define NSTAGE   2
#define GEMM_SMEM (NSTAGE*STAGE_B)     // 81920

__device__ __forceinline__ uint32_t smem_u32(const void* p) {
    uint32_t a;
    asm("{ .reg .u64 t; cvta.to.shared.u64 t, %1; cvt.u32.u64 %0, t; }" : "=r"(a) : "l"(p));
    return a;
}

__device__ __forceinline__ void ldsm_x4(uint32_t (&r)[4], uint32_t addr) {
    asm volatile("ldmatrix.sync.aligned.m8n8.x4.shared.b16 {%0,%1,%2,%3}, [%4];"
                 : "=r"(r[0]), "=r"(r[1]), "=r"(r[2]), "=r"(r[3]) : "r"(addr));
}

__device__ __forceinline__ void mma_bf16(float (&d)[4], const uint32_t (&a)[4],
                                         uint32_t b0, uint32_t b1) {
    asm volatile(
        "mma.sync.aligned.m16n8k16.row.col.f32.bf16.bf16.f32 "
        "{%0,%1,%2,%3}, {%4,%5,%6,%7}, {%8,%9}, {%0,%1,%2,%3};"
        : "+f"(d[0]), "+f"(d[1]), "+f"(d[2]), "+f"(d[3])
        : "r"(a[0]), "r"(a[1]), "r"(a[2]), "r"(a[3]), "r"(b0), "r"(b1));
}

__device__ __forceinline__ void load_stage(
    uint32_t sb, int stage, int chunk, int tid,
    const __nv_bfloat16* __restrict__ A0, const __nv_bfloat16* __restrict__ A1,
    const __nv_bfloat16* __restrict__ B0, const __nv_bfloat16* __restrict__ B1, int K)
{
    const __nv_bfloat16* mats[4] = {A0, A1, B0, B1};
    uint32_t stage_base = sb + (uint32_t)stage * STAGE_B;
    #pragma unroll
    for (int m = 0; m < 4; m++) {
        const __nv_bfloat16* gp = mats[m] + chunk * BKC;
        uint32_t tb = stage_base + m * TILE_PB;
        #pragma unroll
        for (int it = 0; it < 2; it++) {
            int ch = it * 256 + tid;        // 0..511
            int r  = ch >> 2;               // 0..127
            int cc = ch & 3;                // 16B chunk within row
            uint32_t so = tb + (uint32_t)(r * (RS*2) + cc * 16);
            const void* ga = gp + (size_t)r * K + cc * 8;
            asm volatile("cp.async.cg.shared.global [%0], [%1], 16;\n" :: "r"(so), "l"(ga));
        }
    }
}

template<int EPI>
__global__ __launch_bounds__(256, 2) void hmma_gemm(
    const __nv_bfloat16* __restrict__ Ahi, const __nv_bfloat16* __restrict__ Alo,
    const __nv_bfloat16* __restrict__ Bhi, const __nv_bfloat16* __restrict__ Blo,
    float* __restrict__ Cf, const float* __restrict__ X,
    __nv_bfloat16* __restrict__ Chi, __nv_bfloat16* __restrict__ Clo,
    int M, int N, int K)
{
    extern __shared__ char smem[];
    uint32_t sb = smem_u32(smem);
    const int tid  = threadIdx.x;
    const int wid  = tid >> 5;
    const int lane = tid & 31;
    const int bx = blockIdx.x, by = blockIdx.y;
    const int wm = (wid >> 2) * 64;   // 0 or 64
    const int wn = (wid & 3) * 32;    // 0,32,64,96

    const __nv_bfloat16* A0 = Ahi + (size_t)by * 128 * K;
    const __nv_bfloat16* A1 = Alo + (size_t)by * 128 * K;
    const __nv_bfloat16* B0 = Bhi + (size_t)bx * 128 * K;
    const __nv_bfloat16* B1 = Blo + (size_t)bx * 128 * K;

    float d[4][4][4];  // [mi][ni][reg]
    #pragma unroll
    for (int i = 0; i < 4; i++)
        #pragma unroll
        for (int j = 0; j < 4; j++)
            #pragma unroll
            for (int r = 0; r < 4; r++) d[i][j][r] = 0.0f;

    // ldmatrix per-lane address components (byte offsets within a tile)
    const int a_row = lane & 15;                       // + wm + mi*16
    const int a_cb  = (lane >> 4) * 16;                // k-chunk byte
    const int b_row = (lane & 7) | ((lane >> 1) & 8);  // + wn + nb*16
    const int b_cb  = ((lane >> 3) & 1) * 16;

    const int NC = K / BKC;

    load_stage(sb, 0, 0, tid, A0, A1, B0, B1, K);
    asm volatile("cp.async.commit_group;\n" ::: "memory");

    for (int c = 0; c < NC; c++) {
        if (c + 1 < NC)
            load_stage(sb, (c + 1) & 1, c + 1, tid, A0, A1, B0, B1, K);
        asm volatile("cp.async.commit_group;\n" ::: "memory");
        asm volatile("cp.async.wait_group 1;\n" ::: "memory");
        __syncthreads();

        uint32_t st = sb + (uint32_t)(c & 1) * STAGE_B;
        uint32_t ah_b = st;
        uint32_t al_b = st + TILE_PB;
        uint32_t bh_b = st + 2*TILE_PB;
        uint32_t bl_b = st + 3*TILE_PB;

        #pragma unroll
        for (int ks = 0; ks < 2; ks++) {
            #pragma unroll
            for (int nb = 0; nb < 2; nb++) {
                uint32_t bh[4], bl[4];
                uint32_t boff = (uint32_t)((wn + nb*16 + b_row) * (RS*2) + b_cb + ks*32);
                ldsm_x4(bh, bh_b + boff);
                ldsm_x4(bl, bl_b + boff);
                #pragma unroll
                for (int mi = 0; mi < 4; mi++) {
                    uint32_t ah[4], al[4];
                    uint32_t aoff = (uint32_t)((wm + mi*16 + a_row) * (RS*2) + a_cb + ks*32);
                    ldsm_x4(ah, ah_b + aoff);
                    ldsm_x4(al, al_b + aoff);
                    int n0 = nb*2, n1 = nb*2 + 1;
                    mma_bf16(d[mi][n0], ah, bh[0], bh[1]);   // hi*hi
                    mma_bf16(d[mi][n0], ah, bl[0], bl[1]);   // hi*lo
                    mma_bf16(d[mi][n0], al, bh[0], bh[1]);   // lo*hi
                    mma_bf16(d[mi][n1], ah, bh[2], bh[3]);
                    mma_bf16(d[mi][n1], ah, bl[2], bl[3]);
                    mma_bf16(d[mi][n1], al, bh[2], bh[3]);
                }
            }
        }
        __syncthreads();
    }

    // -------- epilogue --------
    const int q  = lane >> 2;
    const int tq = lane & 3;
    #pragma unroll
    for (int mi = 0; mi < 4; mi++) {
        int row0 = by*128 + wm + mi*16 + q;
        #pragma unroll
        for (int ni = 0; ni < 4; ni++) {
            int col = bx*128 + wn + ni*8 + tq*2;
            size_t off0 = (size_t)row0 * N + col;
            size_t off1 = off0 + (size_t)8 * N;
            float v0 = d[mi][ni][0], v1 = d[mi][ni][1];
            float v2 = d[mi][ni][2], v3 = d[mi][ni][3];
            if (EPI == 0) {
                *(float2*)(Cf + off0) = make_float2(v0, v1);
                *(float2*)(Cf + off1) = make_float2(v2, v3);
            } else if (EPI == 1) {
                float2 x0 = *(const float2*)(X + off0);
                float2 x1 = *(const float2*)(X + off1);
                *(float2*)(Cf + off0) = make_float2(v0 + x0.x, v1 + x0.y);
                *(float2*)(Cf + off1) = make_float2(v2 + x1.x, v3 + x1.y);
            } else {  // EPI 3
                float2 x0 = *(const float2*)(X + off0);
                float2 x1 = *(const float2*)(X + off1);
                store_hl2(Chi, Clo, off0, v0 * silu_f(x0.x), v1 * silu_f(x0.y));
                store_hl2(Chi, Clo, off1, v2 * silu_f(x1.x), v3 * silu_f(x1.y));
            }
        }
    }
}

// ================= flash attention (fp32, causal, GQA) =========================
#define ATTN_SMEM ((128*64 + 128*64 + 64*128 + 64*64) * 4)

__global__ __launch_bounds__(256) void attn_kernel(
    const float* __restrict__ qkv, float* __restrict__ out)
{
    extern __shared__ float sm[];
    float* Qt = sm;                 // [128][64] transposed
    float* Kt = sm + 128*64;        // [128][64] transposed
    float* Vs = Kt + 128*64;        // [64][128]
    float* Ps = Vs + 64*128;        // [64][64]

    int q0 = blockIdx.x * 64;
    int h  = blockIdx.y;
    int b  = blockIdx.z;
    int kvh = h >> 2;
    int tid = threadIdx.x;
    int tx = tid & 15, ty = tid >> 4;
    const float scale = rsqrtf((float)EMBED);

    #pragma unroll
    for (int i = 0; i < 8; i++) {
        int e = tid + i * 256;
        int r = e >> 5;
        int c4 = (e & 31) * 4;
        float4 v = *(const float4*)(qkv + (size_t)(b*SEQ + q0 + r) * QKV_N + h*HD + c4);
        Qt[(c4+0)*64 + r] = v.x;
        Qt[(c4+1)*64 + r] = v.y;
        Qt[(c4+2)*64 + r] = v.z;
        Qt[(c4+3)*64 + r] = v.w;
    }

    float m_i[4], l_i[4], O[4][8];
    #pragma unroll
    for (int i = 0; i < 4; i++) {
        m_i[i] = -1e30f; l_i[i] = 0.0f;
        #pragma unroll
        for (int j = 0; j < 8; j++) O[i][j] = 0.0f;
    }

    int ktiles = blockIdx.x + 1;
    for (int kt = 0; kt < ktiles; kt++) {
        int k0 = kt * 64;
        __syncthreads();
        #pragma unroll
        for (int i = 0; i < 8; i++) {
            int e = tid + i * 256;
            int r = e >> 5;
            int c4 = (e & 31) * 4;
            size_t base = (size_t)(b*SEQ + k0 + r) * QKV_N;
            float4 kv4 = *(const float4*)(qkv + base + NH*HD + kvh*HD + c4);
            Kt[(c4+0)*64 + r] = kv4.x;
            Kt[(c4+1)*64 + r] = kv4.y;
            Kt[(c4+2)*64 + r] = kv4.z;
            Kt[(c4+3)*64 + r] = kv4.w;
            float4 vv4 = *(const float4*)(qkv + base + (NH+NKV)*HD + kvh*HD + c4);
            *(float4*)(Vs + r*128 + c4) = vv4;
        }
        __syncthreads();

        float s[4][4];
        #pragma unroll
        for (int i = 0; i < 4; i++)
            #pragma unroll
            for (int j = 0; j < 4; j++) s[i][j] = 0.0f;
        for (int dgl = 0; dgl < 128; dgl++) {
            float4 qa = *(float4*)(Qt + dgl*64 + ty*4);
            float4 kb = *(float4*)(Kt + dgl*64 + tx*4);
            float qr[4] = {qa.x, qa.y, qa.z, qa.w};
            float kr[4] = {kb.x, kb.y, kb.z, kb.w};
            #pragma unroll
            for (int i = 0; i < 4; i++)
                #pragma unroll
                for (int j = 0; j < 4; j++)
                    s[i][j] = fmaf(qr[i], kr[j], s[i][j]);
        }
        bool diag = (kt == blockIdx.x);
        #pragma unroll
        for (int i = 0; i < 4; i++) {
            int rg = q0 + ty*4 + i;
            #pragma unroll
            for (int j = 0; j < 4; j++) {
                s[i][j] *= scale;
                if (diag && (k0 + tx*4 + j > rg)) s[i][j] = -1e30f;
            }
        }
        #pragma unroll
        for (int i = 0; i < 4; i++) {
            float mt = fmaxf(fmaxf(s[i][0], s[i][1]), fmaxf(s[i][2], s[i][3]));
            #pragma unroll
            for (int m = 8; m; m >>= 1) mt = fmaxf(mt, __shfl_xor_sync(0xffffffffu, mt, m));
            float mn = fmaxf(m_i[i], mt);
            float corr = __expf(m_i[i] - mn);
            float lad = 0.0f;
            #pragma unroll
            for (int j = 0; j < 4; j++) {
                float p = __expf(s[i][j] - mn);
                Ps[(ty*4 + i)*64 + tx*4 + j] = p;
                lad += p;
            }
            #pragma unroll
            for (int m = 8; m; m >>= 1) lad += __shfl_xor_sync(0xffffffffu, lad, m);
            l_i[i] = l_i[i] * corr + lad;
            m_i[i] = mn;
            #pragma unroll
            for (int j = 0; j < 8; j++) O[i][j] *= corr;
        }
        __syncthreads();
        for (int c = 0; c < 64; c++) {
            float4 v0 = *(float4*)(Vs + c*128 + tx*8);
            float4 v1 = *(float4*)(Vs + c*128 + tx*8 + 4);
            #pragma unroll
            for (int i = 0; i < 4; i++) {
                float p = Ps[(ty*4 + i)*64 + c];
                O[i][0] = fmaf(p, v0.x, O[i][0]);
                O[i][1] = fmaf(p, v0.y, O[i][1]);
                O[i][2] = fmaf(p, v0.z, O[i][2]);
                O[i][3] = fmaf(p, v0.w, O[i][3]);
                O[i][4] = fmaf(p, v1.x, O[i][4]);
                O[i][5] = fmaf(p, v1.y, O[i][5]);
                O[i][6] = fmaf(p, v1.z, O[i][6]);
                O[i][7] = fmaf(p, v1.w, O[i][7]);
            }
        }
    }

    #pragma unroll
    for (int i = 0; i < 4; i++) {
        float inv = 1.0f / l_i[i];
        int r = q0 + ty*4 + i;
        float* op = out + (size_t)(b*SEQ + r) * EMBED + h*HD + tx*8;
        float4 o0 = make_float4(O[i][0]*inv, O[i][1]*inv, O[i][2]*inv, O[i][3]*inv);
        float4 o1 = make_float4(O[i][4]*inv, O[i][5]*inv, O[i][6]*inv, O[i][7]*inv);
        *(float4*)op       = o0;
        *(float4*)(op + 4) = o1;
    }
}

// ================= launcher ====================================================
extern "C" void kernel_launch(void* const* d_in, const int* in_sizes, int n_in,
                              void* d_out, int out_size)
{
    const float* x      = (const float*)d_in[0];
    const float* freqs  = (const float*)d_in[2];
    const float* w_qkv  = (const float*)d_in[4];
    const float* w_fc   = (const float*)d_in[5];
    const float* w1     = (const float*)d_in[6];
    const float* w2     = (const float*)d_in[7];
    const float* w3     = (const float*)d_in[8];
    const float* attn_w = (const float*)d_in[9];
    const float* ff_w   = (const float*)d_in[10];
    float* out = (float*)d_out;

    float *qkv, *attn, *h2, *ff1;
    __nv_bfloat16 *nhi, *nlo, *ahi, *alo, *fhi, *flo;
    __nv_bfloat16 *wqh, *wql, *wfh, *wfl, *w1h, *w1l, *w2h, *w2l, *w3h, *w3l;
    cudaGetSymbolAddress((void**)&qkv,  g_qkv);
    cudaGetSymbolAddress((void**)&attn, g_attn);
    cudaGetSymbolAddress((void**)&h2,   g_h2);
    cudaGetSymbolAddress((void**)&ff1,  g_ff1);
    cudaGetSymbolAddress((void**)&nhi,  g_nhi);  cudaGetSymbolAddress((void**)&nlo, g_nlo);
    cudaGetSymbolAddress((void**)&ahi,  g_ahi);  cudaGetSymbolAddress((void**)&alo, g_alo);
    cudaGetSymbolAddress((void**)&fhi,  g_fhi);  cudaGetSymbolAddress((void**)&flo, g_flo);
    cudaGetSymbolAddress((void**)&wqh,  g_wqkv_h); cudaGetSymbolAddress((void**)&wql, g_wqkv_l);
    cudaGetSymbolAddress((void**)&wfh,  g_wfc_h);  cudaGetSymbolAddress((void**)&wfl, g_wfc_l);
    cudaGetSymbolAddress((void**)&w1h,  g_w1_h);   cudaGetSymbolAddress((void**)&w1l, g_w1_l);
    cudaGetSymbolAddress((void**)&w2h,  g_w2_h);   cudaGetSymbolAddress((void**)&w2l, g_w2_l);
    cudaGetSymbolAddress((void**)&w3h,  g_w3_h);   cudaGetSymbolAddress((void**)&w3l, g_w3_l);

    cudaFuncSetAttribute((const void*)attn_kernel,
                         cudaFuncAttributeMaxDynamicSharedMemorySize, ATTN_SMEM);
    cudaFuncSetAttribute((const void*)hmma_gemm<0>,
                         cudaFuncAttributeMaxDynamicSharedMemorySize, GEMM_SMEM);
    cudaFuncSetAttribute((const void*)hmma_gemm<1>,
                         cudaFuncAttributeMaxDynamicSharedMemorySize, GEMM_SMEM);
    cudaFuncSetAttribute((const void*)hmma_gemm<3>,
                         cudaFuncAttributeMaxDynamicSharedMemorySize, GEMM_SMEM);

    // weight hi/lo conversion
    cvt_hl<<<(QKV_N*EMBED/4 + 255)/256, 256>>>(w_qkv, wqh, wql, QKV_N*EMBED/4);
    cvt_hl<<<(EMBED*EMBED/4 + 255)/256, 256>>>(w_fc,  wfh, wfl, EMBED*EMBED/4);
    cvt_hl<<<(FF*EMBED/4 + 255)/256, 256>>>(w1, w1h, w1l, FF*EMBED/4);
    cvt_hl<<<(FF*EMBED/4 + 255)/256, 256>>>(w2, w2h, w2l, FF*EMBED/4);
    cvt_hl<<<(EMBED*FF/4 + 255)/256, 256>>>(w3, w3h, w3l, EMBED*FF/4);

    // 1) g = rmsnorm(x) -> hi/lo
    rmsnorm_hl<<<ROWS, 256>>>(x, attn_w, nhi, nlo);
    // 2) qkv = g @ w_qkv^T (fp32 out)
    hmma_gemm<0><<<dim3(QKV_N/128, ROWS/128), 256, GEMM_SMEM>>>(
        nhi, nlo, wqh, wql, qkv, nullptr, nullptr, nullptr, ROWS, QKV_N, EMBED);
    // 3) RoPE
    rope_kernel<<<(ROWS*(NH+NKV)*64 + 255)/256, 256>>>(qkv, freqs);
    // 4) attention (fp32)
    attn_kernel<<<dim3(SEQ/64, NH, BATCH), 256, ATTN_SMEM>>>(qkv, attn);
    // 5) attn -> hi/lo
    cvt_hl<<<(ROWS*EMBED/4 + 255)/256, 256>>>(attn, ahi, alo, ROWS*EMBED/4);
    // 6) h2 = x + attn @ w_fc^T
    hmma_gemm<1><<<dim3(EMBED/128, ROWS/128), 256, GEMM_SMEM>>>(
        ahi, alo, wfh, wfl, h2, x, nullptr, nullptr, ROWS, EMBED, EMBED);
    // 7) g2 = rmsnorm(h2) -> hi/lo
    rmsnorm_hl<<<ROWS, 256>>>(h2, ff_w, nhi, nlo);
    // 8) ff1 = g2 @ w1^T (fp32)
    hmma_gemm<0><<<dim3(FF/128, ROWS/128), 256, GEMM_SMEM>>>(
        nhi, nlo, w1h, w1l, ff1, nullptr, nullptr, nullptr, ROWS, FF, EMBED);
    // 9) ff = silu(ff1) * (g2 @ w2^T) -> hi/lo
    hmma_gemm<3><<<dim3(FF/128, ROWS/128), 256, GEMM_SMEM>>>(
        nhi, nlo, w2h, w2l, nullptr, ff1, fhi, flo, ROWS, FF, EMBED);
    // 10) out = h2 + ff @ w3^T
    hmma_gemm<1><<<dim3(EMBED/128, ROWS/128), 256, GEMM_SMEM>>>(
        fhi, flo, w3h, w3l, out, h2, nullptr, nullptr, ROWS, EMBED, FF);
}

// round 6
// speedup vs baseline: 2.8330x; 1.4006x over previous
#include <cuda_runtime.h>
#include <cuda_bf16.h>
#include <math.h>
#include <cstdint>

// Problem constants
#define BATCH 2
#define SEQ   2048
#define EMBED 2048
#define NH    16
#define NKV   4
#define HD    128
#define FF    5632
#define ROWS  (BATCH*SEQ)          // 4096
#define QKV_N ((NH + 2*NKV)*HD)    // 3072

// ================= scratch (static device globals) =============================
__device__ float g_qkv [ROWS*QKV_N];
__device__ float g_h2  [ROWS*EMBED];
__device__ float g_ff1 [ROWS*FF];
__device__ __nv_bfloat16 g_nhi[ROWS*EMBED], g_nlo[ROWS*EMBED];
__device__ __nv_bfloat16 g_ahi[ROWS*EMBED], g_alo[ROWS*EMBED];
__device__ __nv_bfloat16 g_fhi[ROWS*FF],    g_flo[ROWS*FF];
__device__ __nv_bfloat16 g_qh[ROWS*NH*HD],  g_ql[ROWS*NH*HD];
__device__ __nv_bfloat16 g_kh[ROWS*NKV*HD], g_kl[ROWS*NKV*HD];
__device__ __nv_bfloat16 g_vh[ROWS*NKV*HD], g_vl[ROWS*NKV*HD];   // transposed [b,kh,d,s]
__device__ __nv_bfloat16 g_wqkv_h[QKV_N*EMBED], g_wqkv_l[QKV_N*EMBED];
__device__ __nv_bfloat16 g_wfc_h[EMBED*EMBED],  g_wfc_l[EMBED*EMBED];
__device__ __nv_bfloat16 g_w1_h[FF*EMBED],      g_w1_l[FF*EMBED];
__device__ __nv_bfloat16 g_w2_h[FF*EMBED],      g_w2_l[FF*EMBED];
__device__ __nv_bfloat16 g_w3_h[EMBED*FF],      g_w3_l[EMBED*FF];

// ================= helpers =====================================================
__device__ __forceinline__ float silu_f(float z) { return z / (1.0f + __expf(-z)); }

__device__ __forceinline__ uint32_t smem_u32(const void* p) {
    uint32_t a;
    asm("{ .reg .u64 t; cvta.to.shared.u64 t, %1; cvt.u32.u64 %0, t; }" : "=r"(a) : "l"(p));
    return a;
}
__device__ __forceinline__ void cpa16(uint32_t so, const void* ga) {
    asm volatile("cp.async.cg.shared.global [%0], [%1], 16;\n" :: "r"(so), "l"(ga));
}
__device__ __forceinline__ void ldsm_x4(uint32_t (&r)[4], uint32_t addr) {
    asm volatile("ldmatrix.sync.aligned.m8n8.x4.shared.b16 {%0,%1,%2,%3}, [%4];"
                 : "=r"(r[0]), "=r"(r[1]), "=r"(r[2]), "=r"(r[3]) : "r"(addr));
}
__device__ __forceinline__ void mma_bf16(float (&d)[4], const uint32_t (&a)[4],
                                         uint32_t b0, uint32_t b1) {
    asm volatile(
        "mma.sync.aligned.m16n8k16.row.col.f32.bf16.bf16.f32 "
        "{%0,%1,%2,%3}, {%4,%5,%6,%7}, {%8,%9}, {%0,%1,%2,%3};"
        : "+f"(d[0]), "+f"(d[1]), "+f"(d[2]), "+f"(d[3])
        : "r"(a[0]), "r"(a[1]), "r"(a[2]), "r"(a[3]), "r"(b0), "r"(b1));
}
// pack two fp32 -> bf16x2 (lo -> low half, hi -> high half)
__device__ __forceinline__ uint32_t packbf(float lo, float hi) {
    uint32_t d;
    asm("cvt.rn.bf16x2.f32 %0, %1, %2;" : "=r"(d) : "f"(hi), "f"(lo));
    return d;
}

__device__ __forceinline__ void store_hl4(__nv_bfloat16* __restrict__ hi,
                                          __nv_bfloat16* __restrict__ lo,
                                          size_t idx, float a, float b, float c, float d)
{
    __nv_bfloat16 h0 = __float2bfloat16(a), h1 = __float2bfloat16(b);
    __nv_bfloat16 h2 = __float2bfloat16(c), h3 = __float2bfloat16(d);
    __nv_bfloat16 l0 = __float2bfloat16(a - __bfloat162float(h0));
    __nv_bfloat16 l1 = __float2bfloat16(b - __bfloat162float(h1));
    __nv_bfloat16 l2 = __float2bfloat16(c - __bfloat162float(h2));
    __nv_bfloat16 l3 = __float2bfloat16(d - __bfloat162float(h3));
    __nv_bfloat162 p;
    p.x = h0; p.y = h1; *(__nv_bfloat162*)(hi + idx)     = p;
    p.x = h2; p.y = h3; *(__nv_bfloat162*)(hi + idx + 2) = p;
    p.x = l0; p.y = l1; *(__nv_bfloat162*)(lo + idx)     = p;
    p.x = l2; p.y = l3; *(__nv_bfloat162*)(lo + idx + 2) = p;
}

__device__ __forceinline__ void store_hl2(__nv_bfloat16* __restrict__ hi,
                                          __nv_bfloat16* __restrict__ lo,
                                          size_t idx, float a, float b)
{
    __nv_bfloat16 h0 = __float2bfloat16(a), h1 = __float2bfloat16(b);
    __nv_bfloat16 l0 = __float2bfloat16(a - __bfloat162float(h0));
    __nv_bfloat16 l1 = __float2bfloat16(b - __bfloat162float(h1));
    __nv_bfloat162 p;
    p.x = h0; p.y = h1; *(__nv_bfloat162*)(hi + idx) = p;
    p.x = l0; p.y = l1; *(__nv_bfloat162*)(lo + idx) = p;
}

// fp32 -> (hi, lo) bf16 split
__global__ __launch_bounds__(256) void cvt_hl(
    const float* __restrict__ src, __nv_bfloat16* __restrict__ hi,
    __nv_bfloat16* __restrict__ lo, int n4)
{
    int i = blockIdx.x * 256 + threadIdx.x;
    if (i >= n4) return;
    float4 v = ((const float4*)src)[i];
    store_hl4(hi, lo, (size_t)i * 4, v.x, v.y, v.z, v.w);
}

// rmsnorm with hi/lo bf16 output
__global__ __launch_bounds__(256) void rmsnorm_hl(
    const float* __restrict__ x, const float* __restrict__ w,
    __nv_bfloat16* __restrict__ hi, __nv_bfloat16* __restrict__ lo)
{
    int row = blockIdx.x;
    const float4* xr = (const float4*)(x + (size_t)row * EMBED);
    int t = threadIdx.x;
    float4 v0 = xr[t];
    float4 v1 = xr[t + 256];
    float ss = v0.x*v0.x + v0.y*v0.y + v0.z*v0.z + v0.w*v0.w
             + v1.x*v1.x + v1.y*v1.y + v1.z*v1.z + v1.w*v1.w;
    #pragma unroll
    for (int m = 16; m; m >>= 1) ss += __shfl_xor_sync(0xffffffffu, ss, m);
    __shared__ float red[8];
    if ((t & 31) == 0) red[t >> 5] = ss;
    __syncthreads();
    float tot = red[0]+red[1]+red[2]+red[3]+red[4]+red[5]+red[6]+red[7];
    float r = rsqrtf(tot * (1.0f/EMBED) + 1e-5f);
    const float4* wr = (const float4*)w;
    float4 w0 = wr[t], w1 = wr[t + 256];
    size_t base = (size_t)row * EMBED;
    store_hl4(hi, lo, base + t*4,        v0.x*r*w0.x, v0.y*r*w0.y, v0.z*r*w0.z, v0.w*r*w0.w);
    store_hl4(hi, lo, base + 1024 + t*4, v1.x*r*w1.x, v1.y*r*w1.y, v1.z*r*w1.z, v1.w*r*w1.w);
}

// ---------------- RoPE + hi/lo split of Q,K into head-major layouts ------------
__global__ __launch_bounds__(256) void rope_split(
    const float* __restrict__ qkv, const float* __restrict__ freqs,
    __nv_bfloat16* __restrict__ qh, __nv_bfloat16* __restrict__ ql,
    __nv_bfloat16* __restrict__ kh, __nv_bfloat16* __restrict__ kl)
{
    int idx = blockIdx.x * 256 + threadIdx.x;
    if (idx >= ROWS * (NH + NKV) * 64) return;
    int p    = idx & 63;
    int rem  = idx >> 6;
    int head = rem % (NH + NKV);
    int row  = rem / (NH + NKV);
    int s    = row & (SEQ - 1);
    int b    = row >> 11;
    int col  = (head < NH) ? head*HD + 2*p : NH*HD + (head - NH)*HD + 2*p;
    float2 f = *(const float2*)(freqs + s*HD + 2*p);
    float2 v = *(const float2*)(qkv + (size_t)row * QKV_N + col);
    float n0 = v.x * f.x - v.y * f.y;
    float n1 = v.y * f.x + v.x * f.y;
    if (head < NH) {
        size_t o = ((size_t)(b*NH + head) * SEQ + s) * HD + 2*p;
        store_hl2(qh, ql, o, n0, n1);
    } else {
        size_t o = ((size_t)(b*NKV + head - NH) * SEQ + s) * HD + 2*p;
        store_hl2(kh, kl, o, n0, n1);
    }
}

// ---------------- V: transpose to [b,kh,d,s] + hi/lo split ---------------------
__global__ __launch_bounds__(256) void v_split_t(
    const float* __restrict__ qkv,
    __nv_bfloat16* __restrict__ vh, __nv_bfloat16* __restrict__ vl)
{
    __shared__ float tile[32][33];
    int s0 = blockIdx.x * 32, d0 = blockIdx.y * 32;
    int b  = blockIdx.z >> 2, kh = blockIdx.z & 3;
    int tx = threadIdx.x & 31, ty = threadIdx.x >> 5;   // 32 x 8
    #pragma unroll
    for (int i = 0; i < 4; i++) {
        int s = s0 + ty + i*8;
        tile[ty + i*8][tx] = qkv[(size_t)(b*SEQ + s) * QKV_N + (NH+NKV)*HD + kh*HD + d0 + tx];
    }
    __syncthreads();
    #pragma unroll
    for (int i = 0; i < 4; i++) {
        int d = d0 + ty + i*8;
        float v = tile[tx][ty + i*8];
        size_t o = ((size_t)(b*NKV + kh) * HD + d) * SEQ + s0 + tx;
        __nv_bfloat16 h = __float2bfloat16(v);
        vh[o] = h;
        vl[o] = __float2bfloat16(v - __bfloat162float(h));
    }
}

// ================= HMMA bf16x3 GEMM (unchanged from R5) ========================
#define BKC      32
#define RS       40
#define TILE_PB  (128*RS*2)
#define STAGE_B  (4*TILE_PB)
#define NSTAGE   2
#define GEMM_SMEM (NSTAGE*STAGE_B)     // 81920

__device__ __forceinline__ void load_stage(
    uint32_t sb, int stage, int chunk, int tid,
    const __nv_bfloat16* __restrict__ A0, const __nv_bfloat16* __restrict__ A1,
    const __nv_bfloat16* __restrict__ B0, const __nv_bfloat16* __restrict__ B1, int K)
{
    const __nv_bfloat16* mats[4] = {A0, A1, B0, B1};
    uint32_t stage_base = sb + (uint32_t)stage * STAGE_B;
    #pragma unroll
    for (int m = 0; m < 4; m++) {
        const __nv_bfloat16* gp = mats[m] + chunk * BKC;
        uint32_t tb = stage_base + m * TILE_PB;
        #pragma unroll
        for (int it = 0; it < 2; it++) {
            int ch = it * 256 + tid;
            int r  = ch >> 2;
            int cc = ch & 3;
            uint32_t so = tb + (uint32_t)(r * (RS*2) + cc * 16);
            cpa16(so, gp + (size_t)r * K + cc * 8);
        }
    }
}

template<int EPI>
__global__ __launch_bounds__(256, 2) void hmma_gemm(
    const __nv_bfloat16* __restrict__ Ahi, const __nv_bfloat16* __restrict__ Alo,
    const __nv_bfloat16* __restrict__ Bhi, const __nv_bfloat16* __restrict__ Blo,
    float* __restrict__ Cf, const float* __restrict__ X,
    __nv_bfloat16* __restrict__ Chi, __nv_bfloat16* __restrict__ Clo,
    int M, int N, int K)
{
    extern __shared__ char smem[];
    uint32_t sb = smem_u32(smem);
    const int tid  = threadIdx.x;
    const int wid  = tid >> 5;
    const int lane = tid & 31;
    const int bx = blockIdx.x, by = blockIdx.y;
    const int wm = (wid >> 2) * 64;
    const int wn = (wid & 3) * 32;

    const __nv_bfloat16* A0 = Ahi + (size_t)by * 128 * K;
    const __nv_bfloat16* A1 = Alo + (size_t)by * 128 * K;
    const __nv_bfloat16* B0 = Bhi + (size_t)bx * 128 * K;
    const __nv_bfloat16* B1 = Blo + (size_t)bx * 128 * K;

    float d[4][4][4];
    #pragma unroll
    for (int i = 0; i < 4; i++)
        #pragma unroll
        for (int j = 0; j < 4; j++)
            #pragma unroll
            for (int r = 0; r < 4; r++) d[i][j][r] = 0.0f;

    const int a_row = lane & 15;
    const int a_cb  = (lane >> 4) * 16;
    const int b_row = (lane & 7) | ((lane >> 1) & 8);
    const int b_cb  = ((lane >> 3) & 1) * 16;

    const int NC = K / BKC;

    load_stage(sb, 0, 0, tid, A0, A1, B0, B1, K);
    asm volatile("cp.async.commit_group;\n" ::: "memory");

    for (int c = 0; c < NC; c++) {
        if (c + 1 < NC)
            load_stage(sb, (c + 1) & 1, c + 1, tid, A0, A1, B0, B1, K);
        asm volatile("cp.async.commit_group;\n" ::: "memory");
        asm volatile("cp.async.wait_group 1;\n" ::: "memory");
        __syncthreads();

        uint32_t st = sb + (uint32_t)(c & 1) * STAGE_B;
        uint32_t ah_b = st;
        uint32_t al_b = st + TILE_PB;
        uint32_t bh_b = st + 2*TILE_PB;
        uint32_t bl_b = st + 3*TILE_PB;

        #pragma unroll
        for (int ks = 0; ks < 2; ks++) {
            #pragma unroll
            for (int nb = 0; nb < 2; nb++) {
                uint32_t bh[4], bl[4];
                uint32_t boff = (uint32_t)((wn + nb*16 + b_row) * (RS*2) + b_cb + ks*32);
                ldsm_x4(bh, bh_b + boff);
                ldsm_x4(bl, bl_b + boff);
                #pragma unroll
                for (int mi = 0; mi < 4; mi++) {
                    uint32_t ah[4], al[4];
                    uint32_t aoff = (uint32_t)((wm + mi*16 + a_row) * (RS*2) + a_cb + ks*32);
                    ldsm_x4(ah, ah_b + aoff);
                    ldsm_x4(al, al_b + aoff);
                    int n0 = nb*2, n1 = nb*2 + 1;
                    mma_bf16(d[mi][n0], ah, bh[0], bh[1]);
                    mma_bf16(d[mi][n0], ah, bl[0], bl[1]);
                    mma_bf16(d[mi][n0], al, bh[0], bh[1]);
                    mma_bf16(d[mi][n1], ah, bh[2], bh[3]);
                    mma_bf16(d[mi][n1], ah, bl[2], bl[3]);
                    mma_bf16(d[mi][n1], al, bh[2], bh[3]);
                }
            }
        }
        __syncthreads();
    }

    const int q  = lane >> 2;
    const int tq = lane & 3;
    #pragma unroll
    for (int mi = 0; mi < 4; mi++) {
        int row0 = by*128 + wm + mi*16 + q;
        #pragma unroll
        for (int ni = 0; ni < 4; ni++) {
            int col = bx*128 + wn + ni*8 + tq*2;
            size_t off0 = (size_t)row0 * N + col;
            size_t off1 = off0 + (size_t)8 * N;
            float v0 = d[mi][ni][0], v1 = d[mi][ni][1];
            float v2 = d[mi][ni][2], v3 = d[mi][ni][3];
            if (EPI == 0) {
                *(float2*)(Cf + off0) = make_float2(v0, v1);
                *(float2*)(Cf + off1) = make_float2(v2, v3);
            } else if (EPI == 1) {
                float2 x0 = *(const float2*)(X + off0);
                float2 x1 = *(const float2*)(X + off1);
                *(float2*)(Cf + off0) = make_float2(v0 + x0.x, v1 + x0.y);
                *(float2*)(Cf + off1) = make_float2(v2 + x1.x, v3 + x1.y);
            } else {
                float2 x0 = *(const float2*)(X + off0);
                float2 x1 = *(const float2*)(X + off1);
                store_hl2(Chi, Clo, off0, v0 * silu_f(x0.x), v1 * silu_f(x0.y));
                store_hl2(Chi, Clo, off1, v2 * silu_f(x1.x), v3 * silu_f(x1.y));
            }
        }
    }
}

// ================= HMMA flash attention (bf16x3, causal, GQA) ==================
// CTA: 128 q-rows, 8 warps (16 q each). K-tiles of 64 keys.
// smem: Qh|Ql (128x128, RS 136) Kh|Kl (64x128, RS 136) Vh|Vl transposed (128x64, RS 72)
#define AQ_RS   136
#define AV_RS   72
#define AQT_B   (128*AQ_RS*2)    // 34816
#define AKT_B   (64*AQ_RS*2)     // 17408
#define AVT_B   (128*AV_RS*2)    // 18432
#define ATTN_SMEM (2*AQT_B + 2*AKT_B + 2*AVT_B)   // 141312

__global__ __launch_bounds__(256, 1) void attn_hmma(
    const __nv_bfloat16* __restrict__ Qh, const __nv_bfloat16* __restrict__ Ql,
    const __nv_bfloat16* __restrict__ Kh, const __nv_bfloat16* __restrict__ Kl,
    const __nv_bfloat16* __restrict__ Vh, const __nv_bfloat16* __restrict__ Vl,
    __nv_bfloat16* __restrict__ Ohi, __nv_bfloat16* __restrict__ Olo)
{
    extern __shared__ char smem[];
    uint32_t sb = smem_u32(smem);
    uint32_t q_h = sb,            q_l = sb + AQT_B;
    uint32_t k_h = q_l + AQT_B,   k_l = k_h + AKT_B;
    uint32_t v_h = k_l + AKT_B,   v_l = v_h + AVT_B;

    const int tid = threadIdx.x, wid = tid >> 5, lane = tid & 31;
    const int bx = blockIdx.x, h = blockIdx.y, b = blockIdx.z;
    const int kvh = h >> 2;
    const int q0 = bx * 128;

    const __nv_bfloat16* gQh = Qh + ((size_t)(b*NH + h) * SEQ + q0) * HD;
    const __nv_bfloat16* gQl = Ql + ((size_t)(b*NH + h) * SEQ + q0) * HD;
    const __nv_bfloat16* gKh = Kh + (size_t)(b*NKV + kvh) * SEQ * HD;
    const __nv_bfloat16* gKl = Kl + (size_t)(b*NKV + kvh) * SEQ * HD;
    const __nv_bfloat16* gVh = Vh + (size_t)(b*NKV + kvh) * HD * SEQ;
    const __nv_bfloat16* gVl = Vl + (size_t)(b*NKV + kvh) * HD * SEQ;

    // load Q tile: 128 rows x 16 chunks of 16B, hi + lo
    #pragma unroll
    for (int i = 0; i < 8; i++) {
        int ch = i * 256 + tid;
        int r = ch >> 4, cc = ch & 15;
        uint32_t so = (uint32_t)(r * (AQ_RS*2) + cc * 16);
        cpa16(q_h + so, gQh + (size_t)r * HD + cc * 8);
        cpa16(q_l + so, gQl + (size_t)r * HD + cc * 8);
    }
    asm volatile("cp.async.commit_group;\n" ::: "memory");

    float O[16][4];
    #pragma unroll
    for (int i = 0; i < 16; i++)
        #pragma unroll
        for (int j = 0; j < 4; j++) O[i][j] = 0.0f;
    float m0 = -1e30f, m1 = -1e30f, l0 = 0.0f, l1 = 0.0f;

    const int a_row = lane & 15;
    const int a_cb  = (lane >> 4) * 16;
    const int b_row = (lane & 7) | ((lane >> 1) & 8);
    const int b_cb  = ((lane >> 3) & 1) * 16;
    const int r0g = q0 + wid*16 + (lane >> 2);
    const int r1g = r0g + 8;
    const float scale = rsqrtf((float)EMBED);

    const int ktiles = 2*bx + 2;
    for (int kt = 0; kt < ktiles; kt++) {
        int k0 = kt * 64;
        __syncthreads();   // previous tile's compute done before overwriting K/V
        #pragma unroll
        for (int i = 0; i < 4; i++) {      // K: 64 rows x 16 chunks
            int ch = i * 256 + tid;
            int r = ch >> 4, cc = ch & 15;
            uint32_t so = (uint32_t)(r * (AQ_RS*2) + cc * 16);
            cpa16(k_h + so, gKh + (size_t)(k0 + r) * HD + cc * 8);
            cpa16(k_l + so, gKl + (size_t)(k0 + r) * HD + cc * 8);
        }
        #pragma unroll
        for (int i = 0; i < 4; i++) {      // Vt: 128 rows x 8 chunks
            int ch = i * 256 + tid;
            int r = ch >> 3, cc = ch & 7;
            uint32_t so = (uint32_t)(r * (AV_RS*2) + cc * 16);
            cpa16(v_h + so, gVh + (size_t)r * SEQ + k0 + cc * 8);
            cpa16(v_l + so, gVl + (size_t)r * SEQ + k0 + cc * 8);
        }
        asm volatile("cp.async.commit_group;\n" ::: "memory");
        asm volatile("cp.async.wait_group 0;\n" ::: "memory");
        __syncthreads();

        // ---- scores S(16q x 64k) = Q K^T (bf16x3) ----
        float S[8][4];
        #pragma unroll
        for (int i = 0; i < 8; i++)
            #pragma unroll
            for (int j = 0; j < 4; j++) S[i][j] = 0.0f;

        #pragma unroll
        for (int kk = 0; kk < 8; kk++) {
            uint32_t ah[4], al[4];
            uint32_t aoff = (uint32_t)((wid*16 + a_row) * (AQ_RS*2) + a_cb + kk*32);
            ldsm_x4(ah, q_h + aoff);
            ldsm_x4(al, q_l + aoff);
            #pragma unroll
            for (int np = 0; np < 4; np++) {
                uint32_t bh[4], bl[4];
                uint32_t boff = (uint32_t)((np*16 + b_row) * (AQ_RS*2) + b_cb + kk*32);
                ldsm_x4(bh, k_h + boff);
                ldsm_x4(bl, k_l + boff);
                mma_bf16(S[2*np],   ah, bh[0], bh[1]);
                mma_bf16(S[2*np],   ah, bl[0], bl[1]);
                mma_bf16(S[2*np],   al, bh[0], bh[1]);
                mma_bf16(S[2*np+1], ah, bh[2], bh[3]);
                mma_bf16(S[2*np+1], ah, bl[2], bl[3]);
                mma_bf16(S[2*np+1], al, bh[2], bh[3]);
            }
        }

        // ---- scale + causal mask ----
        #pragma unroll
        for (int ni = 0; ni < 8; ni++) {
            int c0 = k0 + ni*8 + 2*(lane & 3);
            S[ni][0] = (c0     > r0g) ? -1e30f : S[ni][0] * scale;
            S[ni][1] = (c0 + 1 > r0g) ? -1e30f : S[ni][1] * scale;
            S[ni][2] = (c0     > r1g) ? -1e30f : S[ni][2] * scale;
            S[ni][3] = (c0 + 1 > r1g) ? -1e30f : S[ni][3] * scale;
        }

        // ---- online softmax (rows split over 4 lanes: shfl 1,2) ----
        float mx0 = -1e30f, mx1 = -1e30f;
        #pragma unroll
        for (int ni = 0; ni < 8; ni++) {
            mx0 = fmaxf(mx0, fmaxf(S[ni][0], S[ni][1]));
            mx1 = fmaxf(mx1, fmaxf(S[ni][2], S[ni][3]));
        }
        mx0 = fmaxf(mx0, __shfl_xor_sync(0xffffffffu, mx0, 1));
        mx0 = fmaxf(mx0, __shfl_xor_sync(0xffffffffu, mx0, 2));
        mx1 = fmaxf(mx1, __shfl_xor_sync(0xffffffffu, mx1, 1));
        mx1 = fmaxf(mx1, __shfl_xor_sync(0xffffffffu, mx1, 2));
        float mn0 = fmaxf(m0, mx0), mn1 = fmaxf(m1, mx1);
        float corr0 = __expf(m0 - mn0), corr1 = __expf(m1 - mn1);
        m0 = mn0; m1 = mn1;

        uint32_t PH[8][2], PL[8][2];
        float ls0 = 0.0f, ls1 = 0.0f;
        #pragma unroll
        for (int ni = 0; ni < 8; ni++) {
            float p0 = __expf(S[ni][0] - mn0);
            float p1 = __expf(S[ni][1] - mn0);
            float p2 = __expf(S[ni][2] - mn1);
            float p3 = __expf(S[ni][3] - mn1);
            ls0 += p0 + p1; ls1 += p2 + p3;
            uint32_t h01 = packbf(p0, p1);
            uint32_t h23 = packbf(p2, p3);
            PH[ni][0] = h01; PH[ni][1] = h23;
            float h0f = __uint_as_float(h01 << 16);
            float h1f = __uint_as_float(h01 & 0xffff0000u);
            float h2f = __uint_as_float(h23 << 16);
            float h3f = __uint_as_float(h23 & 0xffff0000u);
            PL[ni][0] = packbf(p0 - h0f, p1 - h1f);
            PL[ni][1] = packbf(p2 - h2f, p3 - h3f);
        }
        ls0 += __shfl_xor_sync(0xffffffffu, ls0, 1);
        ls0 += __shfl_xor_sync(0xffffffffu, ls0, 2);
        ls1 += __shfl_xor_sync(0xffffffffu, ls1, 1);
        ls1 += __shfl_xor_sync(0xffffffffu, ls1, 2);
        l0 = l0 * corr0 + ls0;
        l1 = l1 * corr1 + ls1;

        #pragma unroll
        for (int nb = 0; nb < 16; nb++) {
            O[nb][0] *= corr0; O[nb][1] *= corr0;
            O[nb][2] *= corr1; O[nb][3] *= corr1;
        }

        // ---- O += P @ V (Vt as B operand; bf16x3) ----
        #pragma unroll
        for (int kc = 0; kc < 4; kc++) {
            uint32_t ah2[4] = {PH[2*kc][0], PH[2*kc][1], PH[2*kc+1][0], PH[2*kc+1][1]};
            uint32_t al2[4] = {PL[2*kc][0], PL[2*kc][1], PL[2*kc+1][0], PL[2*kc+1][1]};
            #pragma unroll
            for (int dp = 0; dp < 8; dp++) {
                uint32_t bh[4], bl[4];
                uint32_t boff = (uint32_t)((dp*16 + b_row) * (AV_RS*2) + b_cb + kc*32);
                ldsm_x4(bh, v_h + boff);
                ldsm_x4(bl, v_l + boff);
                mma_bf16(O[2*dp],   ah2, bh[0], bh[1]);
                mma_bf16(O[2*dp],   al2, bh[0], bh[1]);
                mma_bf16(O[2*dp],   ah2, bl[0], bl[1]);
                mma_bf16(O[2*dp+1], ah2, bh[2], bh[3]);
                mma_bf16(O[2*dp+1], al2, bh[2], bh[3]);
                mma_bf16(O[2*dp+1], ah2, bl[2], bl[3]);
            }
        }
    }

    // ---- epilogue: write hi/lo bf16 attention output ----
    float inv0 = 1.0f / l0, inv1 = 1.0f / l1;
    #pragma unroll
    for (int nb = 0; nb < 16; nb++) {
        int col = h*HD + nb*8 + 2*(lane & 3);
        size_t o0 = ((size_t)(b*SEQ) + r0g) * EMBED + col;
        size_t o1 = ((size_t)(b*SEQ) + r1g) * EMBED + col;
        store_hl2(Ohi, Olo, o0, O[nb][0]*inv0, O[nb][1]*inv0);
        store_hl2(Ohi, Olo, o1, O[nb][2]*inv1, O[nb][3]*inv1);
    }
}

// ================= launcher ====================================================
extern "C" void kernel_launch(void* const* d_in, const int* in_sizes, int n_in,
                              void* d_out, int out_size)
{
    const float* x      = (const float*)d_in[0];
    const float* freqs  = (const float*)d_in[2];
    const float* w_qkv  = (const float*)d_in[4];
    const float* w_fc   = (const float*)d_in[5];
    const float* w1     = (const float*)d_in[6];
    const float* w2     = (const float*)d_in[7];
    const float* w3     = (const float*)d_in[8];
    const float* attn_w = (const float*)d_in[9];
    const float* ff_w   = (const float*)d_in[10];
    float* out = (float*)d_out;

    float *qkv, *h2, *ff1;
    __nv_bfloat16 *nhi, *nlo, *ahi, *alo, *fhi, *flo;
    __nv_bfloat16 *qh, *ql, *kh, *kl, *vh, *vl;
    __nv_bfloat16 *wqh, *wql, *wfh, *wfl, *w1h, *w1l, *w2h, *w2l, *w3h, *w3l;
    cudaGetSymbolAddress((void**)&qkv,  g_qkv);
    cudaGetSymbolAddress((void**)&h2,   g_h2);
    cudaGetSymbolAddress((void**)&ff1,  g_ff1);
    cudaGetSymbolAddress((void**)&nhi,  g_nhi);  cudaGetSymbolAddress((void**)&nlo, g_nlo);
    cudaGetSymbolAddress((void**)&ahi,  g_ahi);  cudaGetSymbolAddress((void**)&alo, g_alo);
    cudaGetSymbolAddress((void**)&fhi,  g_fhi);  cudaGetSymbolAddress((void**)&flo, g_flo);
    cudaGetSymbolAddress((void**)&qh,   g_qh);   cudaGetSymbolAddress((void**)&ql,  g_ql);
    cudaGetSymbolAddress((void**)&kh,   g_kh);   cudaGetSymbolAddress((void**)&kl,  g_kl);
    cudaGetSymbolAddress((void**)&vh,   g_vh);   cudaGetSymbolAddress((void**)&vl,  g_vl);
    cudaGetSymbolAddress((void**)&wqh,  g_wqkv_h); cudaGetSymbolAddress((void**)&wql, g_wqkv_l);
    cudaGetSymbolAddress((void**)&wfh,  g_wfc_h);  cudaGetSymbolAddress((void**)&wfl, g_wfc_l);
    cudaGetSymbolAddress((void**)&w1h,  g_w1_h);   cudaGetSymbolAddress((void**)&w1l, g_w1_l);
    cudaGetSymbolAddress((void**)&w2h,  g_w2_h);   cudaGetSymbolAddress((void**)&w2l, g_w2_l);
    cudaGetSymbolAddress((void**)&w3h,  g_w3_h);   cudaGetSymbolAddress((void**)&w3l, g_w3_l);

    cudaFuncSetAttribute((const void*)attn_hmma,
                         cudaFuncAttributeMaxDynamicSharedMemorySize, ATTN_SMEM);
    cudaFuncSetAttribute((const void*)hmma_gemm<0>,
                         cudaFuncAttributeMaxDynamicSharedMemorySize, GEMM_SMEM);
    cudaFuncSetAttribute((const void*)hmma_gemm<1>,
                         cudaFuncAttributeMaxDynamicSharedMemorySize, GEMM_SMEM);
    cudaFuncSetAttribute((const void*)hmma_gemm<3>,
                         cudaFuncAttributeMaxDynamicSharedMemorySize, GEMM_SMEM);

    // weight hi/lo conversion
    cvt_hl<<<(QKV_N*EMBED/4 + 255)/256, 256>>>(w_qkv, wqh, wql, QKV_N*EMBED/4);
    cvt_hl<<<(EMBED*EMBED/4 + 255)/256, 256>>>(w_fc,  wfh, wfl, EMBED*EMBED/4);
    cvt_hl<<<(FF*EMBED/4 + 255)/256, 256>>>(w1, w1h, w1l, FF*EMBED/4);
    cvt_hl<<<(FF*EMBED/4 + 255)/256, 256>>>(w2, w2h, w2l, FF*EMBED/4);
    cvt_hl<<<(EMBED*FF/4 + 255)/256, 256>>>(w3, w3h, w3l, EMBED*FF/4);

    // 1) g = rmsnorm(x) -> hi/lo
    rmsnorm_hl<<<ROWS, 256>>>(x, attn_w, nhi, nlo);
    // 2) qkv = g @ w_qkv^T (fp32 out)
    hmma_gemm<0><<<dim3(QKV_N/128, ROWS/128), 256, GEMM_SMEM>>>(
        nhi, nlo, wqh, wql, qkv, nullptr, nullptr, nullptr, ROWS, QKV_N, EMBED);
    // 3) RoPE + hi/lo split of Q,K ; V transpose + split
    rope_split<<<(ROWS*(NH+NKV)*64 + 255)/256, 256>>>(qkv, freqs, qh, ql, kh, kl);
    v_split_t<<<dim3(SEQ/32, HD/32, BATCH*NKV), 256>>>(qkv, vh, vl);
    // 4) attention (HMMA bf16x3) -> ahi/alo
    attn_hmma<<<dim3(SEQ/128, NH, BATCH), 256, ATTN_SMEM>>>(
        qh, ql, kh, kl, vh, vl, ahi, alo);
    // 5) h2 = x + attn @ w_fc^T
    hmma_gemm<1><<<dim3(EMBED/128, ROWS/128), 256, GEMM_SMEM>>>(
        ahi, alo, wfh, wfl, h2, x, nullptr, nullptr, ROWS, EMBED, EMBED);
    // 6) g2 = rmsnorm(h2) -> hi/lo
    rmsnorm_hl<<<ROWS, 256>>>(h2, ff_w, nhi, nlo);
    // 7) ff1 = g2 @ w1^T (fp32)
    hmma_gemm<0><<<dim3(FF/128, ROWS/128), 256, GEMM_SMEM>>>(
        nhi, nlo, w1h, w1l, ff1, nullptr, nullptr, nullptr, ROWS, FF, EMBED);
    // 8) ff = silu(ff1) * (g2 @ w2^T) -> hi/lo
    hmma_gemm<3><<<dim3(FF/128, ROWS/128), 256, GEMM_SMEM>>>(
        nhi, nlo, w2h, w2l, nullptr, ff1, fhi, flo, ROWS, FF, EMBED);
    // 9) out = h2 + ff @ w3^T
    hmma_gemm<1><<<dim3(EMBED/128, ROWS/128), 256, GEMM_SMEM>>>(
        fhi, flo, w3h, w3l, out, h2, nullptr, nullptr, ROWS, EMBED, FF);
}